// round 6
// baseline (speedup 1.0000x reference)
#include <cuda_runtime.h>
#include <cstdint>

// ---------------------------------------------------------------------------
// 2-layer GCN:  out = Â( relu( Â(xW1)+b1 ) W2 ) + b2,  Â = D^-1/2 (A+I) D^-1/2
// edge_index is INT32. Self-loop term fused into GEMM epilogue.
// Aggregation: device-built CSR (by dst) + warp-per-node register accumulation
// (NO float atomics). GEMM: 256 thr/block, 8x4 per-thread tile (high occ).
// ---------------------------------------------------------------------------

static constexpr int NN = 100000;
static constexpr int NE = 1600000;

__device__ float g_h1[(size_t)NN * 128];   // x @ W1
__device__ float g_a1[(size_t)NN * 128];   // Â h1 + b1   (pre-ReLU)
__device__ float g_h2[(size_t)NN * 64];    // relu(a1) @ W2
__device__ float g_dis[NN];                // (1+indeg)^-1/2
__device__ int   g_indeg[NN];
__device__ int   g_rowptr[NN + 1];
__device__ int   g_cursor[NN];
__device__ int   g_csrc[NE];               // CSR src ids (grouped by dst)
__device__ float g_cnrm[NE];               // per-slot dis[s]*dis[d]

// ---------------------------------------------------------------------------
// degree / normalization / CSR build
// ---------------------------------------------------------------------------
__global__ void k_zero_indeg() {
    int i = blockIdx.x * blockDim.x + threadIdx.x;
    if (i < NN) g_indeg[i] = 0;
}

__global__ void k_deg_count(const int* __restrict__ ei) {
    int e = blockIdx.x * blockDim.x + threadIdx.x;
    if (e < NE) atomicAdd(&g_indeg[ei[NE + e]], 1);
}

__global__ void k_dis() {
    int i = blockIdx.x * blockDim.x + threadIdx.x;
    if (i < NN) g_dis[i] = rsqrtf((float)(g_indeg[i] + 1));   // +1 self-loop
}

// one-block exclusive scan of indeg -> rowptr (and cursor copy)
__global__ void __launch_bounds__(1024) k_scan() {
    __shared__ int sh[1024];
    const int t  = threadIdx.x;
    const int CH = (NN + 1023) / 1024;       // 98
    const int base = t * CH;

    int sum = 0;
    for (int i = 0; i < CH; i++) {
        int idx = base + i;
        if (idx < NN) sum += g_indeg[idx];
    }
    sh[t] = sum;
    __syncthreads();
    for (int off = 1; off < 1024; off <<= 1) {    // inclusive Hillis-Steele
        int tmp = (t >= off) ? sh[t - off] : 0;
        __syncthreads();
        sh[t] += tmp;
        __syncthreads();
    }
    int run = sh[t] - sum;                        // exclusive offset for chunk
    for (int i = 0; i < CH; i++) {
        int idx = base + i;
        if (idx < NN) {
            g_rowptr[idx] = run;
            g_cursor[idx] = run;
            run += g_indeg[idx];
        }
    }
    if (t == 1023) g_rowptr[NN] = sh[1023];
}

__global__ void k_csr_fill(const int* __restrict__ ei) {
    int e = blockIdx.x * blockDim.x + threadIdx.x;
    if (e < NE) {
        int s = ei[e];
        int d = ei[NE + e];
        int pos = atomicAdd(&g_cursor[d], 1);
        g_csrc[pos] = s;
        g_cnrm[pos] = g_dis[s] * g_dis[d];
    }
}

// ---------------------------------------------------------------------------
// SIMT fp32 GEMM + fused self-loop epilogue.  256 threads, 8x4 tile/thread.
//   H  = A @ W               (raw, source of the gather)
//   O2 = H * dis[row]^2 + b  (aggregation target, fully initialized)
// SRC=0: A=x (param),    H=g_h1, O2=g_a1
// SRC=1: A=g_a1 (+ReLU), H=g_h2, O2=d_out
// ---------------------------------------------------------------------------
template <int BM, int BN, bool RELU, int SRC>
__global__ void __launch_bounds__(256, 4)
k_gemm(const float* __restrict__ Ap, const float* __restrict__ W,
       const float* __restrict__ bias, float* __restrict__ o2p, int M) {
    constexpr int K   = 128;
    constexpr int KC  = 32;
    constexpr int SA  = BM + 4;          // k-major As row stride
    constexpr int NTX = BN / 4;          // threads along N (4 cols each)
    constexpr int NTY = 256 / NTX;       // threads along M (8 rows each)
    static_assert(NTY * 8 == BM, "tile rows");

    __shared__ float As[KC * SA];        // k-major: As[k*SA + m]
    __shared__ float Ws[KC * BN];

    const float* A  = (SRC == 0) ? Ap : g_a1;
    float*       H  = (SRC == 0) ? g_h1 : g_h2;
    float*       O2 = (SRC == 0) ? g_a1 : o2p;

    const int tid = threadIdx.x;
    const int tx  = tid % NTX;
    const int ty  = tid / NTX;
    const int rowbase = blockIdx.x * BM;

    float acc[8][4] = {};

    for (int kk = 0; kk < K; kk += KC) {
        // --- A chunk (BM x 32) -> k-major As, zero-fill rows >= M ---
        {
            constexpr int PT = (BM * 8) / 256;     // float4 per thread
            const float4* A4 = (const float4*)A;
#pragma unroll
            for (int t = 0; t < PT; t++) {
                int f  = tid + t * 256;
                int r  = f >> 3;
                int c4 = f & 7;
                int grow = rowbase + r;
                float4 v = make_float4(0.f, 0.f, 0.f, 0.f);
                if (grow < M) v = A4[(size_t)grow * 32 + (kk >> 2) + c4];
                if (RELU) {
                    v.x = fmaxf(v.x, 0.f); v.y = fmaxf(v.y, 0.f);
                    v.z = fmaxf(v.z, 0.f); v.w = fmaxf(v.w, 0.f);
                }
                As[(c4 * 4 + 0) * SA + r] = v.x;
                As[(c4 * 4 + 1) * SA + r] = v.y;
                As[(c4 * 4 + 2) * SA + r] = v.z;
                As[(c4 * 4 + 3) * SA + r] = v.w;
            }
        }
        // --- W chunk (32 x BN) ---
        {
            constexpr int PT = (KC * BN / 4) / 256;
            const float4* W4  = (const float4*)(W + (size_t)kk * BN);
            float4*       Ws4 = (float4*)Ws;
#pragma unroll
            for (int t = 0; t < PT; t++)
                Ws4[tid + t * 256] = W4[tid + t * 256];
        }
        __syncthreads();

#pragma unroll
        for (int k = 0; k < KC; k++) {
            const float4 a0 = *(const float4*)(As + k * SA + ty * 8);
            const float4 a1 = *(const float4*)(As + k * SA + ty * 8 + 4);
            const float4 bv = ((const float4*)(Ws + k * BN))[tx];
            const float a[8] = {a0.x, a0.y, a0.z, a0.w, a1.x, a1.y, a1.z, a1.w};
            const float b[4] = {bv.x, bv.y, bv.z, bv.w};
#pragma unroll
            for (int i = 0; i < 8; i++)
#pragma unroll
                for (int j = 0; j < 4; j++)
                    acc[i][j] = fmaf(a[i], b[j], acc[i][j]);
        }
        __syncthreads();
    }

    // --- epilogue: H row and O2 = H*dis^2 + bias ---
    const float4 bb = ((const float4*)bias)[tx];
#pragma unroll
    for (int i = 0; i < 8; i++) {
        int grow = rowbase + ty * 8 + i;
        if (grow < M) {
            float s = g_dis[grow];
            s *= s;
            float4 h = make_float4(acc[i][0], acc[i][1], acc[i][2], acc[i][3]);
            ((float4*)(H + (size_t)grow * BN))[tx] = h;
            ((float4*)(O2 + (size_t)grow * BN))[tx] =
                make_float4(fmaf(h.x, s, bb.x), fmaf(h.y, s, bb.y),
                            fmaf(h.z, s, bb.z), fmaf(h.w, s, bb.w));
        }
    }
}

// ---------------------------------------------------------------------------
// aggregation: one warp per node, register accumulation, single RMW. No atomics.
// C=128: g_h1 -> g_a1;  C=64: g_h2 -> outp (d_out)
// ---------------------------------------------------------------------------
template <int C>
__global__ void __launch_bounds__(256) k_agg(float* __restrict__ outp) {
    const float* h;
    float*       out;
    if constexpr (C == 128) { h = g_h1; out = g_a1; }
    else                    { h = g_h2; out = outp; }

    const int w = (blockIdx.x * blockDim.x + threadIdx.x) >> 5;
    if (w >= NN) return;
    const int lane = threadIdx.x & 31;
    const int beg = g_rowptr[w];
    const int end = g_rowptr[w + 1];

    if constexpr (C == 128) {
        const float4* h4 = (const float4*)h;
        float4* o4 = (float4*)out + (size_t)w * 32 + lane;
        float4 acc = *o4;
        int j = beg;
        for (; j + 1 < end; j += 2) {        // 2-way for MLP
            int   s0 = g_csrc[j],     s1 = g_csrc[j + 1];
            float w0 = g_cnrm[j],     w1 = g_cnrm[j + 1];
            float4 v0 = __ldg(h4 + (size_t)s0 * 32 + lane);
            float4 v1 = __ldg(h4 + (size_t)s1 * 32 + lane);
            acc.x = fmaf(v0.x, w0, acc.x); acc.y = fmaf(v0.y, w0, acc.y);
            acc.z = fmaf(v0.z, w0, acc.z); acc.w = fmaf(v0.w, w0, acc.w);
            acc.x = fmaf(v1.x, w1, acc.x); acc.y = fmaf(v1.y, w1, acc.y);
            acc.z = fmaf(v1.z, w1, acc.z); acc.w = fmaf(v1.w, w1, acc.w);
        }
        if (j < end) {
            int   s0 = g_csrc[j];
            float w0 = g_cnrm[j];
            float4 v0 = __ldg(h4 + (size_t)s0 * 32 + lane);
            acc.x = fmaf(v0.x, w0, acc.x); acc.y = fmaf(v0.y, w0, acc.y);
            acc.z = fmaf(v0.z, w0, acc.z); acc.w = fmaf(v0.w, w0, acc.w);
        }
        *o4 = acc;
    } else {
        const float2* h2 = (const float2*)h;
        float2* o2 = (float2*)out + (size_t)w * 32 + lane;
        float2 acc = *o2;
        int j = beg;
        for (; j + 1 < end; j += 2) {
            int   s0 = g_csrc[j],     s1 = g_csrc[j + 1];
            float w0 = g_cnrm[j],     w1 = g_cnrm[j + 1];
            float2 v0 = __ldg(h2 + (size_t)s0 * 32 + lane);
            float2 v1 = __ldg(h2 + (size_t)s1 * 32 + lane);
            acc.x = fmaf(v0.x, w0, acc.x); acc.y = fmaf(v0.y, w0, acc.y);
            acc.x = fmaf(v1.x, w1, acc.x); acc.y = fmaf(v1.y, w1, acc.y);
        }
        if (j < end) {
            int   s0 = g_csrc[j];
            float w0 = g_cnrm[j];
            float2 v0 = __ldg(h2 + (size_t)s0 * 32 + lane);
            acc.x = fmaf(v0.x, w0, acc.x); acc.y = fmaf(v0.y, w0, acc.y);
        }
        *o2 = acc;
    }
}

// ---------------------------------------------------------------------------
extern "C" void kernel_launch(void* const* d_in, const int* in_sizes, int n_in,
                              void* d_out, int out_size) {
    (void)in_sizes; (void)n_in; (void)out_size;
    const float* x  = (const float*)d_in[0];
    const int*   ei = (const int*)d_in[1];     // int32 (JAX x64 disabled)
    const float* W1 = (const float*)d_in[2];
    const float* b1 = (const float*)d_in[3];
    const float* W2 = (const float*)d_in[4];
    const float* b2 = (const float*)d_in[5];
    float* out = (float*)d_out;

    // --- normalization + CSR build ---
    k_zero_indeg<<<(NN + 255) / 256, 256>>>();
    k_deg_count<<<(NE + 255) / 256, 256>>>(ei);
    k_dis<<<(NN + 255) / 256, 256>>>();
    k_scan<<<1, 1024>>>();
    k_csr_fill<<<(NE + 255) / 256, 256>>>(ei);

    // --- layer 1 ---
    k_gemm<64, 128, false, 0><<<(NN + 63) / 64, 256>>>(x, W1, b1, nullptr, NN);
    k_agg<128><<<(NN * 32 + 255) / 256, 256>>>(nullptr);

    // --- layer 2 ---
    k_gemm<128, 64, true, 1><<<(NN + 127) / 128, 256>>>(nullptr, W2, b2, out, NN);
    k_agg<64><<<(NN * 32 + 255) / 256, 256>>>(out);
}

// round 7
// speedup vs baseline: 1.5501x; 1.5501x over previous
#include <cuda_runtime.h>
#include <cstdint>

// ---------------------------------------------------------------------------
// 2-layer GCN:  out = Â( relu( Â(xW1)+b1 ) W2 ) + b2,  Â = D^-1/2 (A+I) D^-1/2
// edge_index is INT32. Self-loop term fused into GEMM epilogue.
// Aggregation: device-built CSR (by dst) + warp-per-node register accumulation
// (NO float atomics). Multi-block scan (3 launches) replaces 1-block scan.
// ---------------------------------------------------------------------------

static constexpr int NN = 100000;
static constexpr int NE = 1600000;
static constexpr int SCAN_B = (NN + 1023) / 1024;   // 98 blocks

__device__ float g_h1[(size_t)NN * 128];   // x @ W1
__device__ float g_a1[(size_t)NN * 128];   // Â h1 + b1   (pre-ReLU)
__device__ float g_h2[(size_t)NN * 64];    // relu(a1) @ W2
__device__ float g_dis[NN];                // (1+indeg)^-1/2
__device__ int   g_indeg[NN];
__device__ int   g_incl[NN];               // per-element inclusive scan (block-local)
__device__ int   g_bsum[SCAN_B];           // per-block totals -> exclusive offsets
__device__ int   g_rowptr[NN + 1];
__device__ int   g_cursor[NN];
__device__ int   g_csrc[NE];               // CSR src ids (grouped by dst)
__device__ float g_cnrm[NE];               // per-slot dis[s]*dis[d]

// ---------------------------------------------------------------------------
// degree / normalization
// ---------------------------------------------------------------------------
__global__ void k_zero_indeg() {
    int i = blockIdx.x * blockDim.x + threadIdx.x;
    if (i < NN) g_indeg[i] = 0;
}

__global__ void k_deg_count(const int* __restrict__ ei) {
    int e = blockIdx.x * blockDim.x + threadIdx.x;
    if (e < NE) atomicAdd(&g_indeg[ei[NE + e]], 1);
}

__global__ void k_dis() {
    int i = blockIdx.x * blockDim.x + threadIdx.x;
    if (i < NN) g_dis[i] = rsqrtf((float)(g_indeg[i] + 1));   // +1 self-loop
}

// ---------------------------------------------------------------------------
// multi-block exclusive scan of indeg -> rowptr (3 launches)
// ---------------------------------------------------------------------------
__global__ void __launch_bounds__(1024) k_scan_blk() {
    __shared__ int sh[1024];
    int t   = threadIdx.x;
    int idx = blockIdx.x * 1024 + t;
    int v   = (idx < NN) ? g_indeg[idx] : 0;
    sh[t] = v;
    __syncthreads();
#pragma unroll
    for (int off = 1; off < 1024; off <<= 1) {
        int tmp = (t >= off) ? sh[t - off] : 0;
        __syncthreads();
        sh[t] += tmp;
        __syncthreads();
    }
    if (idx < NN) g_incl[idx] = sh[t];
    if (t == 1023) g_bsum[blockIdx.x] = sh[1023];
}

__global__ void __launch_bounds__(128) k_scan_top() {
    __shared__ int sh[128];
    int t = threadIdx.x;
    int v = (t < SCAN_B) ? g_bsum[t] : 0;
    sh[t] = v;
    __syncthreads();
#pragma unroll
    for (int off = 1; off < 128; off <<= 1) {
        int tmp = (t >= off) ? sh[t - off] : 0;
        __syncthreads();
        sh[t] += tmp;
        __syncthreads();
    }
    if (t < SCAN_B) g_bsum[t] = sh[t] - v;        // exclusive block offset
    if (t == SCAN_B - 1) g_rowptr[NN] = sh[t];    // total edge count
}

__global__ void __launch_bounds__(1024) k_scan_fin() {
    int idx = blockIdx.x * 1024 + threadIdx.x;
    if (idx < NN) {
        int r = g_incl[idx] - g_indeg[idx] + g_bsum[blockIdx.x];  // exclusive
        g_rowptr[idx] = r;
        g_cursor[idx] = r;
    }
}

__global__ void k_csr_fill(const int* __restrict__ ei) {
    int e = blockIdx.x * blockDim.x + threadIdx.x;
    if (e < NE) {
        int s = ei[e];
        int d = ei[NE + e];
        int pos = atomicAdd(&g_cursor[d], 1);
        g_csrc[pos] = s;
        g_cnrm[pos] = g_dis[s] * g_dis[d];
    }
}

// ---------------------------------------------------------------------------
// SIMT fp32 GEMM + fused self-loop epilogue.  256 threads, 8x4 tile/thread.
//   H  = A @ W               (raw, source of the gather)
//   O2 = H * dis[row]^2 + b  (aggregation target, fully initialized)
// SRC=0: A=x (param),    H=g_h1, O2=g_a1
// SRC=1: A=g_a1 (+ReLU), H=g_h2, O2=d_out
// ---------------------------------------------------------------------------
template <int BM, int BN, bool RELU, int SRC>
__global__ void __launch_bounds__(256, 4)
k_gemm(const float* __restrict__ Ap, const float* __restrict__ W,
       const float* __restrict__ bias, float* __restrict__ o2p, int M) {
    constexpr int K   = 128;
    constexpr int KC  = 32;
    constexpr int SA  = BM + 4;          // k-major As row stride
    constexpr int NTX = BN / 4;          // threads along N (4 cols each)
    constexpr int NTY = 256 / NTX;       // threads along M (8 rows each)
    static_assert(NTY * 8 == BM, "tile rows");

    __shared__ float As[KC * SA];        // k-major: As[k*SA + m]
    __shared__ float Ws[KC * BN];

    const float* A  = (SRC == 0) ? Ap : g_a1;
    float*       H  = (SRC == 0) ? g_h1 : g_h2;
    float*       O2 = (SRC == 0) ? g_a1 : o2p;

    const int tid = threadIdx.x;
    const int tx  = tid % NTX;
    const int ty  = tid / NTX;
    const int rowbase = blockIdx.x * BM;

    float acc[8][4] = {};

    for (int kk = 0; kk < K; kk += KC) {
        {
            constexpr int PT = (BM * 8) / 256;     // float4 per thread
            const float4* A4 = (const float4*)A;
#pragma unroll
            for (int t = 0; t < PT; t++) {
                int f  = tid + t * 256;
                int r  = f >> 3;
                int c4 = f & 7;
                int grow = rowbase + r;
                float4 v = make_float4(0.f, 0.f, 0.f, 0.f);
                if (grow < M) v = A4[(size_t)grow * 32 + (kk >> 2) + c4];
                if (RELU) {
                    v.x = fmaxf(v.x, 0.f); v.y = fmaxf(v.y, 0.f);
                    v.z = fmaxf(v.z, 0.f); v.w = fmaxf(v.w, 0.f);
                }
                As[(c4 * 4 + 0) * SA + r] = v.x;
                As[(c4 * 4 + 1) * SA + r] = v.y;
                As[(c4 * 4 + 2) * SA + r] = v.z;
                As[(c4 * 4 + 3) * SA + r] = v.w;
            }
        }
        {
            constexpr int PT = (KC * BN / 4) / 256;
            const float4* W4  = (const float4*)(W + (size_t)kk * BN);
            float4*       Ws4 = (float4*)Ws;
#pragma unroll
            for (int t = 0; t < PT; t++)
                Ws4[tid + t * 256] = W4[tid + t * 256];
        }
        __syncthreads();

#pragma unroll
        for (int k = 0; k < KC; k++) {
            const float4 a0 = *(const float4*)(As + k * SA + ty * 8);
            const float4 a1 = *(const float4*)(As + k * SA + ty * 8 + 4);
            const float4 bv = ((const float4*)(Ws + k * BN))[tx];
            const float a[8] = {a0.x, a0.y, a0.z, a0.w, a1.x, a1.y, a1.z, a1.w};
            const float b[4] = {bv.x, bv.y, bv.z, bv.w};
#pragma unroll
            for (int i = 0; i < 8; i++)
#pragma unroll
                for (int j = 0; j < 4; j++)
                    acc[i][j] = fmaf(a[i], b[j], acc[i][j]);
        }
        __syncthreads();
    }

    const float4 bb = ((const float4*)bias)[tx];
#pragma unroll
    for (int i = 0; i < 8; i++) {
        int grow = rowbase + ty * 8 + i;
        if (grow < M) {
            float s = g_dis[grow];
            s *= s;
            float4 h = make_float4(acc[i][0], acc[i][1], acc[i][2], acc[i][3]);
            ((float4*)(H + (size_t)grow * BN))[tx] = h;
            ((float4*)(O2 + (size_t)grow * BN))[tx] =
                make_float4(fmaf(h.x, s, bb.x), fmaf(h.y, s, bb.y),
                            fmaf(h.z, s, bb.z), fmaf(h.w, s, bb.w));
        }
    }
}

// ---------------------------------------------------------------------------
// aggregation: one warp per node, register accumulation, single RMW. No atomics.
// C=128: g_h1 -> g_a1;  C=64: g_h2 -> outp (d_out)
// ---------------------------------------------------------------------------
template <int C>
__global__ void __launch_bounds__(256) k_agg(float* __restrict__ outp) {
    const float* h;
    float*       out;
    if constexpr (C == 128) { h = g_h1; out = g_a1; }
    else                    { h = g_h2; out = outp; }

    const int w = (blockIdx.x * blockDim.x + threadIdx.x) >> 5;
    if (w >= NN) return;
    const int lane = threadIdx.x & 31;
    const int beg = g_rowptr[w];
    const int end = g_rowptr[w + 1];

    if constexpr (C == 128) {
        const float4* h4 = (const float4*)h;
        float4* o4 = (float4*)out + (size_t)w * 32 + lane;
        float4 acc = *o4;
        int j = beg;
        for (; j + 3 < end; j += 4) {        // 4-way for MLP
            int   s0 = g_csrc[j],   s1 = g_csrc[j+1], s2 = g_csrc[j+2], s3 = g_csrc[j+3];
            float w0 = g_cnrm[j],   w1 = g_cnrm[j+1], w2 = g_cnrm[j+2], w3 = g_cnrm[j+3];
            float4 v0 = __ldg(h4 + (size_t)s0 * 32 + lane);
            float4 v1 = __ldg(h4 + (size_t)s1 * 32 + lane);
            float4 v2 = __ldg(h4 + (size_t)s2 * 32 + lane);
            float4 v3 = __ldg(h4 + (size_t)s3 * 32 + lane);
            acc.x = fmaf(v0.x, w0, acc.x); acc.y = fmaf(v0.y, w0, acc.y);
            acc.z = fmaf(v0.z, w0, acc.z); acc.w = fmaf(v0.w, w0, acc.w);
            acc.x = fmaf(v1.x, w1, acc.x); acc.y = fmaf(v1.y, w1, acc.y);
            acc.z = fmaf(v1.z, w1, acc.z); acc.w = fmaf(v1.w, w1, acc.w);
            acc.x = fmaf(v2.x, w2, acc.x); acc.y = fmaf(v2.y, w2, acc.y);
            acc.z = fmaf(v2.z, w2, acc.z); acc.w = fmaf(v2.w, w2, acc.w);
            acc.x = fmaf(v3.x, w3, acc.x); acc.y = fmaf(v3.y, w3, acc.y);
            acc.z = fmaf(v3.z, w3, acc.z); acc.w = fmaf(v3.w, w3, acc.w);
        }
        for (; j < end; j++) {
            int   s0 = g_csrc[j];
            float w0 = g_cnrm[j];
            float4 v0 = __ldg(h4 + (size_t)s0 * 32 + lane);
            acc.x = fmaf(v0.x, w0, acc.x); acc.y = fmaf(v0.y, w0, acc.y);
            acc.z = fmaf(v0.z, w0, acc.z); acc.w = fmaf(v0.w, w0, acc.w);
        }
        *o4 = acc;
    } else {
        const float2* h2 = (const float2*)h;
        float2* o2 = (float2*)out + (size_t)w * 32 + lane;
        float2 acc = *o2;
        int j = beg;
        for (; j + 3 < end; j += 4) {
            int   s0 = g_csrc[j],   s1 = g_csrc[j+1], s2 = g_csrc[j+2], s3 = g_csrc[j+3];
            float w0 = g_cnrm[j],   w1 = g_cnrm[j+1], w2 = g_cnrm[j+2], w3 = g_cnrm[j+3];
            float2 v0 = __ldg(h2 + (size_t)s0 * 32 + lane);
            float2 v1 = __ldg(h2 + (size_t)s1 * 32 + lane);
            float2 v2 = __ldg(h2 + (size_t)s2 * 32 + lane);
            float2 v3 = __ldg(h2 + (size_t)s3 * 32 + lane);
            acc.x = fmaf(v0.x, w0, acc.x); acc.y = fmaf(v0.y, w0, acc.y);
            acc.x = fmaf(v1.x, w1, acc.x); acc.y = fmaf(v1.y, w1, acc.y);
            acc.x = fmaf(v2.x, w2, acc.x); acc.y = fmaf(v2.y, w2, acc.y);
            acc.x = fmaf(v3.x, w3, acc.x); acc.y = fmaf(v3.y, w3, acc.y);
        }
        for (; j < end; j++) {
            int   s0 = g_csrc[j];
            float w0 = g_cnrm[j];
            float2 v0 = __ldg(h2 + (size_t)s0 * 32 + lane);
            acc.x = fmaf(v0.x, w0, acc.x); acc.y = fmaf(v0.y, w0, acc.y);
        }
        *o2 = acc;
    }
}

// ---------------------------------------------------------------------------
extern "C" void kernel_launch(void* const* d_in, const int* in_sizes, int n_in,
                              void* d_out, int out_size) {
    (void)in_sizes; (void)n_in; (void)out_size;
    const float* x  = (const float*)d_in[0];
    const int*   ei = (const int*)d_in[1];     // int32 (JAX x64 disabled)
    const float* W1 = (const float*)d_in[2];
    const float* b1 = (const float*)d_in[3];
    const float* W2 = (const float*)d_in[4];
    const float* b2 = (const float*)d_in[5];
    float* out = (float*)d_out;

    // --- normalization + CSR build ---
    k_zero_indeg<<<(NN + 255) / 256, 256>>>();
    k_deg_count<<<(NE + 255) / 256, 256>>>(ei);
    k_dis<<<(NN + 255) / 256, 256>>>();
    k_scan_blk<<<SCAN_B, 1024>>>();
    k_scan_top<<<1, 128>>>();
    k_scan_fin<<<SCAN_B, 1024>>>();
    k_csr_fill<<<(NE + 255) / 256, 256>>>(ei);

    // --- layer 1 ---
    k_gemm<64, 128, false, 0><<<(NN + 63) / 64, 256>>>(x, W1, b1, nullptr, NN);
    k_agg<128><<<(NN * 32 + 255) / 256, 256>>>(nullptr);

    // --- layer 2 ---
    k_gemm<128, 64, true, 1><<<(NN + 127) / 128, 256>>>(nullptr, W2, b2, out, NN);
    k_agg<64><<<(NN * 32 + 255) / 256, 256>>>(out);
}

// round 8
// speedup vs baseline: 1.6231x; 1.0471x over previous
#include <cuda_runtime.h>
#include <cstdint>

// ---------------------------------------------------------------------------
// 2-layer GCN:  out = Â( relu( Â(xW1)+b1 ) W2 ) + b2,  Â = D^-1/2 (A+I) D^-1/2
// edge_index is INT32. Self-loop term fused into GEMM epilogue.
// Aggregation: device-built CSR (by dst) + warp-per-node register accumulation.
// GEMM inner loop uses packed fp32x2 FMA (fma.rn.f32x2) for 2x fp32 throughput.
// ---------------------------------------------------------------------------

static constexpr int NN = 100000;
static constexpr int NE = 1600000;
static constexpr int SCAN_B = (NN + 1023) / 1024;   // 98 blocks

__device__ float g_h1[(size_t)NN * 128];   // x @ W1
__device__ float g_a1[(size_t)NN * 128];   // Â h1 + b1   (pre-ReLU)
__device__ float g_h2[(size_t)NN * 64];    // relu(a1) @ W2
__device__ float g_dis[NN];                // (1+indeg)^-1/2
__device__ int   g_indeg[NN];
__device__ int   g_incl[NN];
__device__ int   g_bsum[SCAN_B];
__device__ int   g_rowptr[NN + 1];
__device__ int   g_cursor[NN];
__device__ int   g_csrc[NE];               // CSR src ids (grouped by dst)
__device__ float g_cnrm[NE];               // per-slot dis[s]*dis[d]

// ---------------------------------------------------------------------------
// packed f32x2 helpers (Blackwell dual-lane fp32 FMA; PTX-only encoding)
// ---------------------------------------------------------------------------
typedef unsigned long long u64;
__device__ __forceinline__ u64 pk2(float lo, float hi) {
    u64 r; asm("mov.b64 %0, {%1, %2};" : "=l"(r) : "f"(lo), "f"(hi)); return r;
}
__device__ __forceinline__ void upk2(float& lo, float& hi, u64 v) {
    asm("mov.b64 {%0, %1}, %2;" : "=f"(lo), "=f"(hi) : "l"(v));
}
__device__ __forceinline__ u64 fma2(u64 a, u64 b, u64 c) {
    u64 d; asm("fma.rn.f32x2 %0, %1, %2, %3;" : "=l"(d) : "l"(a), "l"(b), "l"(c));
    return d;
}

// ---------------------------------------------------------------------------
// degree / normalization
// ---------------------------------------------------------------------------
__global__ void k_zero_indeg() {
    int i = blockIdx.x * blockDim.x + threadIdx.x;
    if (i < NN) g_indeg[i] = 0;
}

__global__ void k_deg_count(const int* __restrict__ ei) {
    int e = blockIdx.x * blockDim.x + threadIdx.x;
    if (e < NE) atomicAdd(&g_indeg[ei[NE + e]], 1);
}

__global__ void k_dis() {
    int i = blockIdx.x * blockDim.x + threadIdx.x;
    if (i < NN) g_dis[i] = rsqrtf((float)(g_indeg[i] + 1));   // +1 self-loop
}

// ---------------------------------------------------------------------------
// multi-block exclusive scan of indeg -> rowptr (3 launches)
// ---------------------------------------------------------------------------
__global__ void __launch_bounds__(1024) k_scan_blk() {
    __shared__ int sh[1024];
    int t   = threadIdx.x;
    int idx = blockIdx.x * 1024 + t;
    int v   = (idx < NN) ? g_indeg[idx] : 0;
    sh[t] = v;
    __syncthreads();
#pragma unroll
    for (int off = 1; off < 1024; off <<= 1) {
        int tmp = (t >= off) ? sh[t - off] : 0;
        __syncthreads();
        sh[t] += tmp;
        __syncthreads();
    }
    if (idx < NN) g_incl[idx] = sh[t];
    if (t == 1023) g_bsum[blockIdx.x] = sh[1023];
}

__global__ void __launch_bounds__(128) k_scan_top() {
    __shared__ int sh[128];
    int t = threadIdx.x;
    int v = (t < SCAN_B) ? g_bsum[t] : 0;
    sh[t] = v;
    __syncthreads();
#pragma unroll
    for (int off = 1; off < 128; off <<= 1) {
        int tmp = (t >= off) ? sh[t - off] : 0;
        __syncthreads();
        sh[t] += tmp;
        __syncthreads();
    }
    if (t < SCAN_B) g_bsum[t] = sh[t] - v;        // exclusive block offset
    if (t == SCAN_B - 1) g_rowptr[NN] = sh[t];
}

__global__ void __launch_bounds__(1024) k_scan_fin() {
    int idx = blockIdx.x * 1024 + threadIdx.x;
    if (idx < NN) {
        int r = g_incl[idx] - g_indeg[idx] + g_bsum[blockIdx.x];
        g_rowptr[idx] = r;
        g_cursor[idx] = r;
    }
}

__global__ void k_csr_fill(const int* __restrict__ ei) {
    int e = blockIdx.x * blockDim.x + threadIdx.x;
    if (e < NE) {
        int s = ei[e];
        int d = ei[NE + e];
        int pos = atomicAdd(&g_cursor[d], 1);
        g_csrc[pos] = s;
        g_cnrm[pos] = g_dis[s] * g_dis[d];
    }
}

// ---------------------------------------------------------------------------
// fp32 GEMM + fused self-loop epilogue. 256 threads, 8x4 tile (as 4x4 pairs).
// Inner loop: fma.rn.f32x2 — pairs along M come free from LDS.128 registers.
//   H  = A @ W               (raw, source of the gather)
//   O2 = H * dis[row]^2 + b  (aggregation target, fully initialized)
// SRC=0: A=x (param),    H=g_h1, O2=g_a1
// SRC=1: A=g_a1 (+ReLU), H=g_h2, O2=d_out
// ---------------------------------------------------------------------------
template <int BM, int BN, bool RELU, int SRC>
__global__ void __launch_bounds__(256, 4)
k_gemm(const float* __restrict__ Ap, const float* __restrict__ W,
       const float* __restrict__ bias, float* __restrict__ o2p, int M) {
    constexpr int K   = 128;
    constexpr int KC  = 32;
    constexpr int SA  = BM + 4;          // k-major As row stride
    constexpr int NTX = BN / 4;          // threads along N (4 cols each)
    constexpr int NTY = 256 / NTX;       // threads along M (8 rows each)
    static_assert(NTY * 8 == BM, "tile rows");

    __shared__ float As[KC * SA];        // k-major: As[k*SA + m]
    __shared__ float Ws[KC * BN];

    const float* A  = (SRC == 0) ? Ap : g_a1;
    float*       H  = (SRC == 0) ? g_h1 : g_h2;
    float*       O2 = (SRC == 0) ? g_a1 : o2p;

    const int tid = threadIdx.x;
    const int tx  = tid % NTX;
    const int ty  = tid / NTX;
    const int rowbase = blockIdx.x * BM;

    u64 acc2[4][4];                      // [m-pair][n]: (acc[2p], acc[2p+1])
#pragma unroll
    for (int p = 0; p < 4; p++)
#pragma unroll
        for (int j = 0; j < 4; j++) acc2[p][j] = 0ull;

    for (int kk = 0; kk < K; kk += KC) {
        {
            constexpr int PT = (BM * 8) / 256;     // float4 per thread
            const float4* A4 = (const float4*)A;
#pragma unroll
            for (int t = 0; t < PT; t++) {
                int f  = tid + t * 256;
                int r  = f >> 3;
                int c4 = f & 7;
                int grow = rowbase + r;
                float4 v = make_float4(0.f, 0.f, 0.f, 0.f);
                if (grow < M) v = A4[(size_t)grow * 32 + (kk >> 2) + c4];
                if (RELU) {
                    v.x = fmaxf(v.x, 0.f); v.y = fmaxf(v.y, 0.f);
                    v.z = fmaxf(v.z, 0.f); v.w = fmaxf(v.w, 0.f);
                }
                As[(c4 * 4 + 0) * SA + r] = v.x;
                As[(c4 * 4 + 1) * SA + r] = v.y;
                As[(c4 * 4 + 2) * SA + r] = v.z;
                As[(c4 * 4 + 3) * SA + r] = v.w;
            }
        }
        {
            constexpr int PT = (KC * BN / 4) / 256;
            const float4* W4  = (const float4*)(W + (size_t)kk * BN);
            float4*       Ws4 = (float4*)Ws;
#pragma unroll
            for (int t = 0; t < PT; t++)
                Ws4[tid + t * 256] = W4[tid + t * 256];
        }
        __syncthreads();

#pragma unroll
        for (int k = 0; k < KC; k++) {
            const float4 a0 = *(const float4*)(As + k * SA + ty * 8);
            const float4 a1 = *(const float4*)(As + k * SA + ty * 8 + 4);
            const float4 bv = ((const float4*)(Ws + k * BN))[tx];
            u64 ap[4] = {pk2(a0.x, a0.y), pk2(a0.z, a0.w),
                         pk2(a1.x, a1.y), pk2(a1.z, a1.w)};
            u64 bp[4] = {pk2(bv.x, bv.x), pk2(bv.y, bv.y),
                         pk2(bv.z, bv.z), pk2(bv.w, bv.w)};
#pragma unroll
            for (int p = 0; p < 4; p++)
#pragma unroll
                for (int j = 0; j < 4; j++)
                    acc2[p][j] = fma2(ap[p], bp[j], acc2[p][j]);
        }
        __syncthreads();
    }

    // --- epilogue: unpack pairs; store H row and O2 = H*dis^2 + bias ---
    const float4 bb = ((const float4*)bias)[tx];
#pragma unroll
    for (int p = 0; p < 4; p++) {
        float lo[4], hi[4];
#pragma unroll
        for (int j = 0; j < 4; j++) upk2(lo[j], hi[j], acc2[p][j]);
#pragma unroll
        for (int half = 0; half < 2; half++) {
            int grow = rowbase + ty * 8 + p * 2 + half;
            if (grow < M) {
                float s = g_dis[grow];
                s *= s;
                const float* v = half ? hi : lo;
                float4 h = make_float4(v[0], v[1], v[2], v[3]);
                ((float4*)(H + (size_t)grow * BN))[tx] = h;
                ((float4*)(O2 + (size_t)grow * BN))[tx] =
                    make_float4(fmaf(h.x, s, bb.x), fmaf(h.y, s, bb.y),
                                fmaf(h.z, s, bb.z), fmaf(h.w, s, bb.w));
            }
        }
    }
}

// ---------------------------------------------------------------------------
// aggregation: one warp per node, register accumulation, single RMW. No atomics.
// ---------------------------------------------------------------------------
template <int C>
__global__ void __launch_bounds__(256) k_agg(float* __restrict__ outp) {
    const float* h;
    float*       out;
    if constexpr (C == 128) { h = g_h1; out = g_a1; }
    else                    { h = g_h2; out = outp; }

    const int w = (blockIdx.x * blockDim.x + threadIdx.x) >> 5;
    if (w >= NN) return;
    const int lane = threadIdx.x & 31;
    const int beg = g_rowptr[w];
    const int end = g_rowptr[w + 1];

    if constexpr (C == 128) {
        const float4* h4 = (const float4*)h;
        float4* o4 = (float4*)out + (size_t)w * 32 + lane;
        float4 acc = *o4;
        int j = beg;
        for (; j + 3 < end; j += 4) {        // 4-way for MLP
            int   s0 = g_csrc[j],   s1 = g_csrc[j+1], s2 = g_csrc[j+2], s3 = g_csrc[j+3];
            float w0 = g_cnrm[j],   w1 = g_cnrm[j+1], w2 = g_cnrm[j+2], w3 = g_cnrm[j+3];
            float4 v0 = __ldg(h4 + (size_t)s0 * 32 + lane);
            float4 v1 = __ldg(h4 + (size_t)s1 * 32 + lane);
            float4 v2 = __ldg(h4 + (size_t)s2 * 32 + lane);
            float4 v3 = __ldg(h4 + (size_t)s3 * 32 + lane);
            acc.x = fmaf(v0.x, w0, acc.x); acc.y = fmaf(v0.y, w0, acc.y);
            acc.z = fmaf(v0.z, w0, acc.z); acc.w = fmaf(v0.w, w0, acc.w);
            acc.x = fmaf(v1.x, w1, acc.x); acc.y = fmaf(v1.y, w1, acc.y);
            acc.z = fmaf(v1.z, w1, acc.z); acc.w = fmaf(v1.w, w1, acc.w);
            acc.x = fmaf(v2.x, w2, acc.x); acc.y = fmaf(v2.y, w2, acc.y);
            acc.z = fmaf(v2.z, w2, acc.z); acc.w = fmaf(v2.w, w2, acc.w);
            acc.x = fmaf(v3.x, w3, acc.x); acc.y = fmaf(v3.y, w3, acc.y);
            acc.z = fmaf(v3.z, w3, acc.z); acc.w = fmaf(v3.w, w3, acc.w);
        }
        for (; j < end; j++) {
            int   s0 = g_csrc[j];
            float w0 = g_cnrm[j];
            float4 v0 = __ldg(h4 + (size_t)s0 * 32 + lane);
            acc.x = fmaf(v0.x, w0, acc.x); acc.y = fmaf(v0.y, w0, acc.y);
            acc.z = fmaf(v0.z, w0, acc.z); acc.w = fmaf(v0.w, w0, acc.w);
        }
        *o4 = acc;
    } else {
        const float2* h2 = (const float2*)h;
        float2* o2 = (float2*)out + (size_t)w * 32 + lane;
        float2 acc = *o2;
        int j = beg;
        for (; j + 3 < end; j += 4) {
            int   s0 = g_csrc[j],   s1 = g_csrc[j+1], s2 = g_csrc[j+2], s3 = g_csrc[j+3];
            float w0 = g_cnrm[j],   w1 = g_cnrm[j+1], w2 = g_cnrm[j+2], w3 = g_cnrm[j+3];
            float2 v0 = __ldg(h2 + (size_t)s0 * 32 + lane);
            float2 v1 = __ldg(h2 + (size_t)s1 * 32 + lane);
            float2 v2 = __ldg(h2 + (size_t)s2 * 32 + lane);
            float2 v3 = __ldg(h2 + (size_t)s3 * 32 + lane);
            acc.x = fmaf(v0.x, w0, acc.x); acc.y = fmaf(v0.y, w0, acc.y);
            acc.x = fmaf(v1.x, w1, acc.x); acc.y = fmaf(v1.y, w1, acc.y);
            acc.x = fmaf(v2.x, w2, acc.x); acc.y = fmaf(v2.y, w2, acc.y);
            acc.x = fmaf(v3.x, w3, acc.x); acc.y = fmaf(v3.y, w3, acc.y);
        }
        for (; j < end; j++) {
            int   s0 = g_csrc[j];
            float w0 = g_cnrm[j];
            float2 v0 = __ldg(h2 + (size_t)s0 * 32 + lane);
            acc.x = fmaf(v0.x, w0, acc.x); acc.y = fmaf(v0.y, w0, acc.y);
        }
        *o2 = acc;
    }
}

// ---------------------------------------------------------------------------
extern "C" void kernel_launch(void* const* d_in, const int* in_sizes, int n_in,
                              void* d_out, int out_size) {
    (void)in_sizes; (void)n_in; (void)out_size;
    const float* x  = (const float*)d_in[0];
    const int*   ei = (const int*)d_in[1];     // int32 (JAX x64 disabled)
    const float* W1 = (const float*)d_in[2];
    const float* b1 = (const float*)d_in[3];
    const float* W2 = (const float*)d_in[4];
    const float* b2 = (const float*)d_in[5];
    float* out = (float*)d_out;

    // --- normalization + CSR build ---
    k_zero_indeg<<<(NN + 255) / 256, 256>>>();
    k_deg_count<<<(NE + 255) / 256, 256>>>(ei);
    k_dis<<<(NN + 255) / 256, 256>>>();
    k_scan_blk<<<SCAN_B, 1024>>>();
    k_scan_top<<<1, 128>>>();
    k_scan_fin<<<SCAN_B, 1024>>>();
    k_csr_fill<<<(NE + 255) / 256, 256>>>(ei);

    // --- layer 1 ---
    k_gemm<64, 128, false, 0><<<(NN + 63) / 64, 256>>>(x, W1, b1, nullptr, NN);
    k_agg<128><<<(NN * 32 + 255) / 256, 256>>>(nullptr);

    // --- layer 2 ---
    k_gemm<128, 64, true, 1><<<(NN + 127) / 128, 256>>>(nullptr, W2, b2, out, NN);
    k_agg<64><<<(NN * 32 + 255) / 256, 256>>>(out);
}

// round 9
// speedup vs baseline: 1.7079x; 1.0523x over previous
#include <cuda_runtime.h>
#include <cstdint>

// ---------------------------------------------------------------------------
// 2-layer GCN:  out = Â( relu( Â(xW1)+b1 ) W2 ) + b2,  Â = D^-1/2 (A+I) D^-1/2
// edge_index is INT32.
// GEMM writes only H = A@W (f32x2 FMA inner loop). Aggregation does the full
// Â·H + b:  out = dis[w]*(dis[w]*h[w] + Σ dis[s]*h[s]) + b  (no atomics, CSR).
// CSR build runs on a forked capture stream, overlapped with GEMM1.
// ---------------------------------------------------------------------------

static constexpr int NN = 100000;
static constexpr int NE = 1600000;
static constexpr int SCAN_B = (NN + 1023) / 1024;   // 98 blocks

__device__ float g_h1[(size_t)NN * 128];   // x @ W1
__device__ float g_a1[(size_t)NN * 128];   // Â h1 + b1   (pre-ReLU)
__device__ float g_h2[(size_t)NN * 64];    // relu(a1) @ W2
__device__ float g_dis[NN];                // (1+indeg)^-1/2
__device__ int   g_indeg[NN];
__device__ int   g_incl[NN];
__device__ int   g_bsum[SCAN_B];
__device__ int   g_rowptr[NN + 1];
__device__ int   g_cursor[NN];
__device__ int   g_csrc[NE];               // CSR src ids (grouped by dst)

// ---------------------------------------------------------------------------
// packed f32x2 helpers (Blackwell dual-lane fp32 FMA; PTX-only encoding)
// ---------------------------------------------------------------------------
typedef unsigned long long u64;
__device__ __forceinline__ u64 pk2(float lo, float hi) {
    u64 r; asm("mov.b64 %0, {%1, %2};" : "=l"(r) : "f"(lo), "f"(hi)); return r;
}
__device__ __forceinline__ void upk2(float& lo, float& hi, u64 v) {
    asm("mov.b64 {%0, %1}, %2;" : "=f"(lo), "=f"(hi) : "l"(v));
}
__device__ __forceinline__ u64 fma2(u64 a, u64 b, u64 c) {
    u64 d; asm("fma.rn.f32x2 %0, %1, %2, %3;" : "=l"(d) : "l"(a), "l"(b), "l"(c));
    return d;
}

// ---------------------------------------------------------------------------
// degree / normalization
// ---------------------------------------------------------------------------
__global__ void k_zero_indeg() {
    int i = blockIdx.x * blockDim.x + threadIdx.x;
    if (i < NN) g_indeg[i] = 0;
}

__global__ void k_deg_count(const int* __restrict__ ei) {
    int e = blockIdx.x * blockDim.x + threadIdx.x;
    if (e < NE) atomicAdd(&g_indeg[ei[NE + e]], 1);
}

__global__ void k_dis() {
    int i = blockIdx.x * blockDim.x + threadIdx.x;
    if (i < NN) g_dis[i] = rsqrtf((float)(g_indeg[i] + 1));   // +1 self-loop
}

// ---------------------------------------------------------------------------
// multi-block exclusive scan of indeg -> rowptr (3 launches)
// ---------------------------------------------------------------------------
__global__ void __launch_bounds__(1024) k_scan_blk() {
    __shared__ int sh[1024];
    int t   = threadIdx.x;
    int idx = blockIdx.x * 1024 + t;
    int v   = (idx < NN) ? g_indeg[idx] : 0;
    sh[t] = v;
    __syncthreads();
#pragma unroll
    for (int off = 1; off < 1024; off <<= 1) {
        int tmp = (t >= off) ? sh[t - off] : 0;
        __syncthreads();
        sh[t] += tmp;
        __syncthreads();
    }
    if (idx < NN) g_incl[idx] = sh[t];
    if (t == 1023) g_bsum[blockIdx.x] = sh[1023];
}

__global__ void __launch_bounds__(128) k_scan_top() {
    __shared__ int sh[128];
    int t = threadIdx.x;
    int v = (t < SCAN_B) ? g_bsum[t] : 0;
    sh[t] = v;
    __syncthreads();
#pragma unroll
    for (int off = 1; off < 128; off <<= 1) {
        int tmp = (t >= off) ? sh[t - off] : 0;
        __syncthreads();
        sh[t] += tmp;
        __syncthreads();
    }
    if (t < SCAN_B) g_bsum[t] = sh[t] - v;        // exclusive block offset
    if (t == SCAN_B - 1) g_rowptr[NN] = sh[t];
}

__global__ void __launch_bounds__(1024) k_scan_fin() {
    int idx = blockIdx.x * 1024 + threadIdx.x;
    if (idx < NN) {
        int r = g_incl[idx] - g_indeg[idx] + g_bsum[blockIdx.x];
        g_rowptr[idx] = r;
        g_cursor[idx] = r;
    }
}

__global__ void k_csr_fill(const int* __restrict__ ei) {
    int e = blockIdx.x * blockDim.x + threadIdx.x;
    if (e < NE) {
        int s = ei[e];
        int d = ei[NE + e];
        int pos = atomicAdd(&g_cursor[d], 1);
        g_csrc[pos] = s;
    }
}

// ---------------------------------------------------------------------------
// fp32 GEMM (H = A @ W only). 256 threads, 8x4 tile as 4x4 f32x2 pairs.
// SRC=0: A=x (param),    H=g_h1      SRC=1: A=relu(g_a1), H=g_h2
// ---------------------------------------------------------------------------
template <int BM, int BN, bool RELU, int SRC>
__global__ void __launch_bounds__(256, 4)
k_gemm(const float* __restrict__ Ap, const float* __restrict__ W, int M) {
    constexpr int K   = 128;
    constexpr int KC  = 32;
    constexpr int SA  = BM + 4;          // k-major As row stride
    constexpr int NTX = BN / 4;          // threads along N (4 cols each)
    constexpr int NTY = 256 / NTX;       // threads along M (8 rows each)
    static_assert(NTY * 8 == BM, "tile rows");

    __shared__ float As[KC * SA];        // k-major: As[k*SA + m]
    __shared__ float Ws[KC * BN];

    const float* A = (SRC == 0) ? Ap : g_a1;
    float*       H = (SRC == 0) ? g_h1 : g_h2;

    const int tid = threadIdx.x;
    const int tx  = tid % NTX;
    const int ty  = tid / NTX;
    const int rowbase = blockIdx.x * BM;

    u64 acc2[4][4];
#pragma unroll
    for (int p = 0; p < 4; p++)
#pragma unroll
        for (int j = 0; j < 4; j++) acc2[p][j] = 0ull;

    for (int kk = 0; kk < K; kk += KC) {
        {
            constexpr int PT = (BM * 8) / 256;     // float4 per thread
            const float4* A4 = (const float4*)A;
#pragma unroll
            for (int t = 0; t < PT; t++) {
                int f  = tid + t * 256;
                int r  = f >> 3;
                int c4 = f & 7;
                int grow = rowbase + r;
                float4 v = make_float4(0.f, 0.f, 0.f, 0.f);
                if (grow < M) v = A4[(size_t)grow * 32 + (kk >> 2) + c4];
                if (RELU) {
                    v.x = fmaxf(v.x, 0.f); v.y = fmaxf(v.y, 0.f);
                    v.z = fmaxf(v.z, 0.f); v.w = fmaxf(v.w, 0.f);
                }
                As[(c4 * 4 + 0) * SA + r] = v.x;
                As[(c4 * 4 + 1) * SA + r] = v.y;
                As[(c4 * 4 + 2) * SA + r] = v.z;
                As[(c4 * 4 + 3) * SA + r] = v.w;
            }
        }
        {
            constexpr int PT = (KC * BN / 4) / 256;
            const float4* W4  = (const float4*)(W + (size_t)kk * BN);
            float4*       Ws4 = (float4*)Ws;
#pragma unroll
            for (int t = 0; t < PT; t++)
                Ws4[tid + t * 256] = W4[tid + t * 256];
        }
        __syncthreads();

#pragma unroll
        for (int k = 0; k < KC; k++) {
            const float4 a0 = *(const float4*)(As + k * SA + ty * 8);
            const float4 a1 = *(const float4*)(As + k * SA + ty * 8 + 4);
            const float4 bv = ((const float4*)(Ws + k * BN))[tx];
            u64 ap[4] = {pk2(a0.x, a0.y), pk2(a0.z, a0.w),
                         pk2(a1.x, a1.y), pk2(a1.z, a1.w)};
            u64 bp[4] = {pk2(bv.x, bv.x), pk2(bv.y, bv.y),
                         pk2(bv.z, bv.z), pk2(bv.w, bv.w)};
#pragma unroll
            for (int p = 0; p < 4; p++)
#pragma unroll
                for (int j = 0; j < 4; j++)
                    acc2[p][j] = fma2(ap[p], bp[j], acc2[p][j]);
        }
        __syncthreads();
    }

#pragma unroll
    for (int p = 0; p < 4; p++) {
        float lo[4], hi[4];
#pragma unroll
        for (int j = 0; j < 4; j++) upk2(lo[j], hi[j], acc2[p][j]);
#pragma unroll
        for (int half = 0; half < 2; half++) {
            int grow = rowbase + ty * 8 + p * 2 + half;
            if (grow < M) {
                const float* v = half ? hi : lo;
                ((float4*)(H + (size_t)grow * BN))[tx] =
                    make_float4(v[0], v[1], v[2], v[3]);
            }
        }
    }
}

// ---------------------------------------------------------------------------
// aggregation (full GCN conv from H):
//   out[w] = dis[w] * ( dis[w]*h[w] + Σ_{s in N(w)} dis[s]*h[s] ) + bias
// one warp per node, register accumulation, single store. No atomics.
// C=128: g_h1 -> g_a1;  C=64: g_h2 -> outp (d_out)
// ---------------------------------------------------------------------------
template <int C>
__global__ void __launch_bounds__(256)
k_agg(const float* __restrict__ bias, float* __restrict__ outp) {
    const float* h;
    float*       out;
    if constexpr (C == 128) { h = g_h1; out = g_a1; }
    else                    { h = g_h2; out = outp; }

    const int w = (blockIdx.x * blockDim.x + threadIdx.x) >> 5;
    if (w >= NN) return;
    const int lane = threadIdx.x & 31;
    const int beg = g_rowptr[w];
    const int end = g_rowptr[w + 1];
    const float dw = g_dis[w];

    if constexpr (C == 128) {
        const float4* h4 = (const float4*)h;
        float4 hv = h4[(size_t)w * 32 + lane];
        float4 acc = make_float4(hv.x * dw, hv.y * dw, hv.z * dw, hv.w * dw);
        int j = beg;
        for (; j + 3 < end; j += 4) {        // 4-way for MLP
            int   s0 = g_csrc[j],   s1 = g_csrc[j+1], s2 = g_csrc[j+2], s3 = g_csrc[j+3];
            float w0 = g_dis[s0],   w1 = g_dis[s1],   w2 = g_dis[s2],   w3 = g_dis[s3];
            float4 v0 = __ldg(h4 + (size_t)s0 * 32 + lane);
            float4 v1 = __ldg(h4 + (size_t)s1 * 32 + lane);
            float4 v2 = __ldg(h4 + (size_t)s2 * 32 + lane);
            float4 v3 = __ldg(h4 + (size_t)s3 * 32 + lane);
            acc.x = fmaf(v0.x, w0, acc.x); acc.y = fmaf(v0.y, w0, acc.y);
            acc.z = fmaf(v0.z, w0, acc.z); acc.w = fmaf(v0.w, w0, acc.w);
            acc.x = fmaf(v1.x, w1, acc.x); acc.y = fmaf(v1.y, w1, acc.y);
            acc.z = fmaf(v1.z, w1, acc.z); acc.w = fmaf(v1.w, w1, acc.w);
            acc.x = fmaf(v2.x, w2, acc.x); acc.y = fmaf(v2.y, w2, acc.y);
            acc.z = fmaf(v2.z, w2, acc.z); acc.w = fmaf(v2.w, w2, acc.w);
            acc.x = fmaf(v3.x, w3, acc.x); acc.y = fmaf(v3.y, w3, acc.y);
            acc.z = fmaf(v3.z, w3, acc.z); acc.w = fmaf(v3.w, w3, acc.w);
        }
        for (; j < end; j++) {
            int   s0 = g_csrc[j];
            float w0 = g_dis[s0];
            float4 v0 = __ldg(h4 + (size_t)s0 * 32 + lane);
            acc.x = fmaf(v0.x, w0, acc.x); acc.y = fmaf(v0.y, w0, acc.y);
            acc.z = fmaf(v0.z, w0, acc.z); acc.w = fmaf(v0.w, w0, acc.w);
        }
        const float4 bb = ((const float4*)bias)[lane];
        ((float4*)out)[(size_t)w * 32 + lane] =
            make_float4(fmaf(acc.x, dw, bb.x), fmaf(acc.y, dw, bb.y),
                        fmaf(acc.z, dw, bb.z), fmaf(acc.w, dw, bb.w));
    } else {
        const float2* h2 = (const float2*)h;
        float2 hv = h2[(size_t)w * 32 + lane];
        float2 acc = make_float2(hv.x * dw, hv.y * dw);
        int j = beg;
        for (; j + 3 < end; j += 4) {
            int   s0 = g_csrc[j],   s1 = g_csrc[j+1], s2 = g_csrc[j+2], s3 = g_csrc[j+3];
            float w0 = g_dis[s0],   w1 = g_dis[s1],   w2 = g_dis[s2],   w3 = g_dis[s3];
            float2 v0 = __ldg(h2 + (size_t)s0 * 32 + lane);
            float2 v1 = __ldg(h2 + (size_t)s1 * 32 + lane);
            float2 v2 = __ldg(h2 + (size_t)s2 * 32 + lane);
            float2 v3 = __ldg(h2 + (size_t)s3 * 32 + lane);
            acc.x = fmaf(v0.x, w0, acc.x); acc.y = fmaf(v0.y, w0, acc.y);
            acc.x = fmaf(v1.x, w1, acc.x); acc.y = fmaf(v1.y, w1, acc.y);
            acc.x = fmaf(v2.x, w2, acc.x); acc.y = fmaf(v2.y, w2, acc.y);
            acc.x = fmaf(v3.x, w3, acc.x); acc.y = fmaf(v3.y, w3, acc.y);
        }
        for (; j < end; j++) {
            int   s0 = g_csrc[j];
            float w0 = g_dis[s0];
            float2 v0 = __ldg(h2 + (size_t)s0 * 32 + lane);
            acc.x = fmaf(v0.x, w0, acc.x); acc.y = fmaf(v0.y, w0, acc.y);
        }
        const float2 bb = ((const float2*)bias)[lane];
        ((float2*)out)[(size_t)w * 32 + lane] =
            make_float2(fmaf(acc.x, dw, bb.x), fmaf(acc.y, dw, bb.y));
    }
}

// ---------------------------------------------------------------------------
extern "C" void kernel_launch(void* const* d_in, const int* in_sizes, int n_in,
                              void* d_out, int out_size) {
    (void)in_sizes; (void)n_in; (void)out_size;
    const float* x  = (const float*)d_in[0];
    const int*   ei = (const int*)d_in[1];     // int32 (JAX x64 disabled)
    const float* W1 = (const float*)d_in[2];
    const float* b1 = (const float*)d_in[3];
    const float* W2 = (const float*)d_in[4];
    const float* b2 = (const float*)d_in[5];
    float* out = (float*)d_out;

    // fork-join: CSR build on side stream, overlapped with GEMM1
    cudaStream_t s2;
    cudaEvent_t evFork, evJoin;
    cudaStreamCreateWithFlags(&s2, cudaStreamNonBlocking);
    cudaEventCreateWithFlags(&evFork, cudaEventDisableTiming);
    cudaEventCreateWithFlags(&evJoin, cudaEventDisableTiming);

    cudaEventRecord(evFork, 0);
    cudaStreamWaitEvent(s2, evFork, 0);

    // --- CSR branch (stream s2): degrees, dis, rowptr, fill ---
    k_zero_indeg<<<(NN + 255) / 256, 256, 0, s2>>>();
    k_deg_count<<<(NE + 255) / 256, 256, 0, s2>>>(ei);
    k_dis<<<(NN + 255) / 256, 256, 0, s2>>>();
    k_scan_blk<<<SCAN_B, 1024, 0, s2>>>();
    k_scan_top<<<1, 128, 0, s2>>>();
    k_scan_fin<<<SCAN_B, 1024, 0, s2>>>();
    k_csr_fill<<<(NE + 255) / 256, 256, 0, s2>>>(ei);
    cudaEventRecord(evJoin, s2);

    // --- main branch (stream 0): GEMM1 runs concurrently with CSR build ---
    k_gemm<64, 128, false, 0><<<(NN + 63) / 64, 256>>>(x, W1, NN);
    cudaStreamWaitEvent(0, evJoin, 0);

    k_agg<128><<<(NN * 32 + 255) / 256, 256>>>(b1, nullptr);
    k_gemm<128, 64, true, 1><<<(NN + 127) / 128, 256>>>(nullptr, W2, NN);
    k_agg<64><<<(NN * 32 + 255) / 256, 256>>>(b2, out);

    cudaEventDestroy(evFork);
    cudaEventDestroy(evJoin);
    cudaStreamDestroy(s2);
}

// round 10
// speedup vs baseline: 1.9091x; 1.1178x over previous
#include <cuda_runtime.h>
#include <cuda_fp16.h>
#include <cstdint>

// ---------------------------------------------------------------------------
// 2-layer GCN:  out = Â( relu( Â(xW1)+b1 ) W2 ) + b2,  Â = D^-1/2 (A+I) D^-1/2
// edge_index is INT32.
// GEMM writes H = A@W in FP16 (gather format). Aggregation gathers fp16,
// accumulates fp32:  out = dis[w]*(dis[w]*h[w] + Σ dis[s]*h[s]) + b.
// CSR build on a forked capture stream, overlapped with GEMM1.
// ---------------------------------------------------------------------------

static constexpr int NN = 100000;
static constexpr int NE = 1600000;
static constexpr int SCAN_B = (NN + 1023) / 1024;   // 98 blocks

__device__ __half g_hh1[(size_t)NN * 128];  // x @ W1          (fp16 gather buf)
__device__ float  g_a1[(size_t)NN * 128];   // Â h1 + b1       (fp32, pre-ReLU)
__device__ __half g_hh2[(size_t)NN * 64];   // relu(a1) @ W2   (fp16 gather buf)
__device__ float  g_dis[NN];                // (1+indeg)^-1/2
__device__ int    g_indeg[NN];
__device__ int    g_incl[NN];
__device__ int    g_bsum[SCAN_B];
__device__ int    g_rowptr[NN + 1];
__device__ int    g_cursor[NN];
__device__ int    g_csrc[NE];               // CSR src ids (grouped by dst)

// ---------------------------------------------------------------------------
// packed f32x2 helpers (Blackwell dual-lane fp32 FMA; PTX-only encoding)
// ---------------------------------------------------------------------------
typedef unsigned long long u64;
__device__ __forceinline__ u64 pk2(float lo, float hi) {
    u64 r; asm("mov.b64 %0, {%1, %2};" : "=l"(r) : "f"(lo), "f"(hi)); return r;
}
__device__ __forceinline__ void upk2(float& lo, float& hi, u64 v) {
    asm("mov.b64 {%0, %1}, %2;" : "=f"(lo), "=f"(hi) : "l"(v));
}
__device__ __forceinline__ u64 fma2(u64 a, u64 b, u64 c) {
    u64 d; asm("fma.rn.f32x2 %0, %1, %2, %3;" : "=l"(d) : "l"(a), "l"(b), "l"(c));
    return d;
}

// fp16 pack/unpack
__device__ __forceinline__ unsigned h2u(__half2 h) {
    return *reinterpret_cast<unsigned*>(&h);
}
__device__ __forceinline__ float2 u2f2(unsigned u) {
    return __half22float2(*reinterpret_cast<__half2*>(&u));
}

// ---------------------------------------------------------------------------
// degree / normalization
// ---------------------------------------------------------------------------
__global__ void k_zero_indeg() {
    int i = blockIdx.x * blockDim.x + threadIdx.x;
    if (i < NN) g_indeg[i] = 0;
}

__global__ void k_deg_count(const int* __restrict__ ei) {
    int e = blockIdx.x * blockDim.x + threadIdx.x;
    if (e < NE) atomicAdd(&g_indeg[ei[NE + e]], 1);
}

__global__ void k_dis() {
    int i = blockIdx.x * blockDim.x + threadIdx.x;
    if (i < NN) g_dis[i] = rsqrtf((float)(g_indeg[i] + 1));   // +1 self-loop
}

// ---------------------------------------------------------------------------
// multi-block exclusive scan of indeg -> rowptr (3 launches)
// ---------------------------------------------------------------------------
__global__ void __launch_bounds__(1024) k_scan_blk() {
    __shared__ int sh[1024];
    int t   = threadIdx.x;
    int idx = blockIdx.x * 1024 + t;
    int v   = (idx < NN) ? g_indeg[idx] : 0;
    sh[t] = v;
    __syncthreads();
#pragma unroll
    for (int off = 1; off < 1024; off <<= 1) {
        int tmp = (t >= off) ? sh[t - off] : 0;
        __syncthreads();
        sh[t] += tmp;
        __syncthreads();
    }
    if (idx < NN) g_incl[idx] = sh[t];
    if (t == 1023) g_bsum[blockIdx.x] = sh[1023];
}

__global__ void __launch_bounds__(128) k_scan_top() {
    __shared__ int sh[128];
    int t = threadIdx.x;
    int v = (t < SCAN_B) ? g_bsum[t] : 0;
    sh[t] = v;
    __syncthreads();
#pragma unroll
    for (int off = 1; off < 128; off <<= 1) {
        int tmp = (t >= off) ? sh[t - off] : 0;
        __syncthreads();
        sh[t] += tmp;
        __syncthreads();
    }
    if (t < SCAN_B) g_bsum[t] = sh[t] - v;        // exclusive block offset
    if (t == SCAN_B - 1) g_rowptr[NN] = sh[t];
}

__global__ void __launch_bounds__(1024) k_scan_fin() {
    int idx = blockIdx.x * 1024 + threadIdx.x;
    if (idx < NN) {
        int r = g_incl[idx] - g_indeg[idx] + g_bsum[blockIdx.x];
        g_rowptr[idx] = r;
        g_cursor[idx] = r;
    }
}

__global__ void k_csr_fill(const int* __restrict__ ei) {
    int e = blockIdx.x * blockDim.x + threadIdx.x;
    if (e < NE) {
        int s = ei[e];
        int d = ei[NE + e];
        int pos = atomicAdd(&g_cursor[d], 1);
        g_csrc[pos] = s;
    }
}

// ---------------------------------------------------------------------------
// fp32 GEMM, H stored as FP16. 256 threads, 8x4 tile as 4x4 f32x2 pairs.
// SRC=0: A=x (param),    H=g_hh1      SRC=1: A=relu(g_a1), H=g_hh2
// ---------------------------------------------------------------------------
template <int BM, int BN, bool RELU, int SRC>
__global__ void __launch_bounds__(256, 4)
k_gemm(const float* __restrict__ Ap, const float* __restrict__ W, int M) {
    constexpr int K   = 128;
    constexpr int KC  = 32;
    constexpr int SA  = BM + 4;          // k-major As row stride
    constexpr int NTX = BN / 4;          // threads along N (4 cols each)
    constexpr int NTY = 256 / NTX;       // threads along M (8 rows each)
    static_assert(NTY * 8 == BM, "tile rows");

    __shared__ float As[KC * SA];        // k-major: As[k*SA + m]
    __shared__ float Ws[KC * BN];

    const float* A = (SRC == 0) ? Ap : g_a1;
    __half*      H = (SRC == 0) ? g_hh1 : g_hh2;

    const int tid = threadIdx.x;
    const int tx  = tid % NTX;
    const int ty  = tid / NTX;
    const int rowbase = blockIdx.x * BM;

    u64 acc2[4][4];
#pragma unroll
    for (int p = 0; p < 4; p++)
#pragma unroll
        for (int j = 0; j < 4; j++) acc2[p][j] = 0ull;

    for (int kk = 0; kk < K; kk += KC) {
        {
            constexpr int PT = (BM * 8) / 256;     // float4 per thread
            const float4* A4 = (const float4*)A;
#pragma unroll
            for (int t = 0; t < PT; t++) {
                int f  = tid + t * 256;
                int r  = f >> 3;
                int c4 = f & 7;
                int grow = rowbase + r;
                float4 v = make_float4(0.f, 0.f, 0.f, 0.f);
                if (grow < M) v = A4[(size_t)grow * 32 + (kk >> 2) + c4];
                if (RELU) {
                    v.x = fmaxf(v.x, 0.f); v.y = fmaxf(v.y, 0.f);
                    v.z = fmaxf(v.z, 0.f); v.w = fmaxf(v.w, 0.f);
                }
                As[(c4 * 4 + 0) * SA + r] = v.x;
                As[(c4 * 4 + 1) * SA + r] = v.y;
                As[(c4 * 4 + 2) * SA + r] = v.z;
                As[(c4 * 4 + 3) * SA + r] = v.w;
            }
        }
        {
            constexpr int PT = (KC * BN / 4) / 256;
            const float4* W4  = (const float4*)(W + (size_t)kk * BN);
            float4*       Ws4 = (float4*)Ws;
#pragma unroll
            for (int t = 0; t < PT; t++)
                Ws4[tid + t * 256] = W4[tid + t * 256];
        }
        __syncthreads();

#pragma unroll
        for (int k = 0; k < KC; k++) {
            const float4 a0 = *(const float4*)(As + k * SA + ty * 8);
            const float4 a1 = *(const float4*)(As + k * SA + ty * 8 + 4);
            const float4 bv = ((const float4*)(Ws + k * BN))[tx];
            u64 ap[4] = {pk2(a0.x, a0.y), pk2(a0.z, a0.w),
                         pk2(a1.x, a1.y), pk2(a1.z, a1.w)};
            u64 bp[4] = {pk2(bv.x, bv.x), pk2(bv.y, bv.y),
                         pk2(bv.z, bv.z), pk2(bv.w, bv.w)};
#pragma unroll
            for (int p = 0; p < 4; p++)
#pragma unroll
                for (int j = 0; j < 4; j++)
                    acc2[p][j] = fma2(ap[p], bp[j], acc2[p][j]);
        }
        __syncthreads();
    }

    // --- epilogue: convert to fp16, store uint2 (4 halfs) per thread/row ---
#pragma unroll
    for (int p = 0; p < 4; p++) {
        float lo[4], hi[4];
#pragma unroll
        for (int j = 0; j < 4; j++) upk2(lo[j], hi[j], acc2[p][j]);
#pragma unroll
        for (int half_ = 0; half_ < 2; half_++) {
            int grow = rowbase + ty * 8 + p * 2 + half_;
            if (grow < M) {
                const float* v = half_ ? hi : lo;
                uint2 pk;
                pk.x = h2u(__floats2half2_rn(v[0], v[1]));
                pk.y = h2u(__floats2half2_rn(v[2], v[3]));
                ((uint2*)(H + (size_t)grow * BN))[tx] = pk;
            }
        }
    }
}

// ---------------------------------------------------------------------------
// aggregation (full GCN conv from fp16 H, fp32 accumulate):
//   out[w] = dis[w] * ( dis[w]*h[w] + Σ_{s in N(w)} dis[s]*h[s] ) + bias
// one warp per node. C=128: g_hh1 -> g_a1 (fp32); C=64: g_hh2 -> outp (fp32)
// ---------------------------------------------------------------------------
template <int C>
__global__ void __launch_bounds__(256)
k_agg(const float* __restrict__ bias, float* __restrict__ outp) {
    const __half* h;
    float*        out;
    if constexpr (C == 128) { h = g_hh1; out = g_a1; }
    else                    { h = g_hh2; out = outp; }

    const int w = (blockIdx.x * blockDim.x + threadIdx.x) >> 5;
    if (w >= NN) return;
    const int lane = threadIdx.x & 31;
    const int beg = g_rowptr[w];
    const int end = g_rowptr[w + 1];
    const float dw = g_dis[w];

    if constexpr (C == 128) {
        const uint2* h8 = (const uint2*)h;          // 4 halfs per uint2, 32/row
        uint2 raw = h8[(size_t)w * 32 + lane];
        float2 f0 = u2f2(raw.x), f1 = u2f2(raw.y);
        float4 acc = make_float4(f0.x * dw, f0.y * dw, f1.x * dw, f1.y * dw);
        int j = beg;
        for (; j + 3 < end; j += 4) {               // 4-way for MLP
            int   s0 = g_csrc[j],   s1 = g_csrc[j+1], s2 = g_csrc[j+2], s3 = g_csrc[j+3];
            float w0 = g_dis[s0],   w1 = g_dis[s1],   w2 = g_dis[s2],   w3 = g_dis[s3];
            uint2 r0 = __ldg(h8 + (size_t)s0 * 32 + lane);
            uint2 r1 = __ldg(h8 + (size_t)s1 * 32 + lane);
            uint2 r2 = __ldg(h8 + (size_t)s2 * 32 + lane);
            uint2 r3 = __ldg(h8 + (size_t)s3 * 32 + lane);
            float2 a0 = u2f2(r0.x), b0 = u2f2(r0.y);
            float2 a1 = u2f2(r1.x), b1 = u2f2(r1.y);
            float2 a2 = u2f2(r2.x), b2 = u2f2(r2.y);
            float2 a3 = u2f2(r3.x), b3 = u2f2(r3.y);
            acc.x = fmaf(a0.x, w0, acc.x); acc.y = fmaf(a0.y, w0, acc.y);
            acc.z = fmaf(b0.x, w0, acc.z); acc.w = fmaf(b0.y, w0, acc.w);
            acc.x = fmaf(a1.x, w1, acc.x); acc.y = fmaf(a1.y, w1, acc.y);
            acc.z = fmaf(b1.x, w1, acc.z); acc.w = fmaf(b1.y, w1, acc.w);
            acc.x = fmaf(a2.x, w2, acc.x); acc.y = fmaf(a2.y, w2, acc.y);
            acc.z = fmaf(b2.x, w2, acc.z); acc.w = fmaf(b2.y, w2, acc.w);
            acc.x = fmaf(a3.x, w3, acc.x); acc.y = fmaf(a3.y, w3, acc.y);
            acc.z = fmaf(b3.x, w3, acc.z); acc.w = fmaf(b3.y, w3, acc.w);
        }
        for (; j < end; j++) {
            int   s0 = g_csrc[j];
            float w0 = g_dis[s0];
            uint2 r0 = __ldg(h8 + (size_t)s0 * 32 + lane);
            float2 a0 = u2f2(r0.x), b0 = u2f2(r0.y);
            acc.x = fmaf(a0.x, w0, acc.x); acc.y = fmaf(a0.y, w0, acc.y);
            acc.z = fmaf(b0.x, w0, acc.z); acc.w = fmaf(b0.y, w0, acc.w);
        }
        const float4 bb = ((const float4*)bias)[lane];
        ((float4*)out)[(size_t)w * 32 + lane] =
            make_float4(fmaf(acc.x, dw, bb.x), fmaf(acc.y, dw, bb.y),
                        fmaf(acc.z, dw, bb.z), fmaf(acc.w, dw, bb.w));
    } else {
        const unsigned* h4 = (const unsigned*)h;    // 2 halfs per u32, 32/row
        float2 hv = u2f2(h4[(size_t)w * 32 + lane]);
        float2 acc = make_float2(hv.x * dw, hv.y * dw);
        int j = beg;
        for (; j + 3 < end; j += 4) {
            int   s0 = g_csrc[j],   s1 = g_csrc[j+1], s2 = g_csrc[j+2], s3 = g_csrc[j+3];
            float w0 = g_dis[s0],   w1 = g_dis[s1],   w2 = g_dis[s2],   w3 = g_dis[s3];
            float2 v0 = u2f2(__ldg(h4 + (size_t)s0 * 32 + lane));
            float2 v1 = u2f2(__ldg(h4 + (size_t)s1 * 32 + lane));
            float2 v2 = u2f2(__ldg(h4 + (size_t)s2 * 32 + lane));
            float2 v3 = u2f2(__ldg(h4 + (size_t)s3 * 32 + lane));
            acc.x = fmaf(v0.x, w0, acc.x); acc.y = fmaf(v0.y, w0, acc.y);
            acc.x = fmaf(v1.x, w1, acc.x); acc.y = fmaf(v1.y, w1, acc.y);
            acc.x = fmaf(v2.x, w2, acc.x); acc.y = fmaf(v2.y, w2, acc.y);
            acc.x = fmaf(v3.x, w3, acc.x); acc.y = fmaf(v3.y, w3, acc.y);
        }
        for (; j < end; j++) {
            int   s0 = g_csrc[j];
            float w0 = g_dis[s0];
            float2 v0 = u2f2(__ldg(h4 + (size_t)s0 * 32 + lane));
            acc.x = fmaf(v0.x, w0, acc.x); acc.y = fmaf(v0.y, w0, acc.y);
        }
        const float2 bb = ((const float2*)bias)[lane];
        ((float2*)out)[(size_t)w * 32 + lane] =
            make_float2(fmaf(acc.x, dw, bb.x), fmaf(acc.y, dw, bb.y));
    }
}

// ---------------------------------------------------------------------------
extern "C" void kernel_launch(void* const* d_in, const int* in_sizes, int n_in,
                              void* d_out, int out_size) {
    (void)in_sizes; (void)n_in; (void)out_size;
    const float* x  = (const float*)d_in[0];
    const int*   ei = (const int*)d_in[1];     // int32 (JAX x64 disabled)
    const float* W1 = (const float*)d_in[2];
    const float* b1 = (const float*)d_in[3];
    const float* W2 = (const float*)d_in[4];
    const float* b2 = (const float*)d_in[5];
    float* out = (float*)d_out;

    // fork-join: CSR build on side stream, overlapped with GEMM1
    cudaStream_t s2;
    cudaEvent_t evFork, evJoin;
    cudaStreamCreateWithFlags(&s2, cudaStreamNonBlocking);
    cudaEventCreateWithFlags(&evFork, cudaEventDisableTiming);
    cudaEventCreateWithFlags(&evJoin, cudaEventDisableTiming);

    cudaEventRecord(evFork, 0);
    cudaStreamWaitEvent(s2, evFork, 0);

    // --- CSR branch (stream s2): degrees, dis, rowptr, fill ---
    k_zero_indeg<<<(NN + 255) / 256, 256, 0, s2>>>();
    k_deg_count<<<(NE + 255) / 256, 256, 0, s2>>>(ei);
    k_dis<<<(NN + 255) / 256, 256, 0, s2>>>();
    k_scan_blk<<<SCAN_B, 1024, 0, s2>>>();
    k_scan_top<<<1, 128, 0, s2>>>();
    k_scan_fin<<<SCAN_B, 1024, 0, s2>>>();
    k_csr_fill<<<(NE + 255) / 256, 256, 0, s2>>>(ei);
    cudaEventRecord(evJoin, s2);

    // --- main branch (stream 0): GEMM1 runs concurrently with CSR build ---
    k_gemm<64, 128, false, 0><<<(NN + 63) / 64, 256>>>(x, W1, NN);
    cudaStreamWaitEvent(0, evJoin, 0);

    k_agg<128><<<(NN * 32 + 255) / 256, 256>>>(b1, nullptr);
    k_gemm<128, 64, true, 1><<<(NN + 127) / 128, 256>>>(nullptr, W2, NN);
    k_agg<64><<<(NN * 32 + 255) / 256, 256>>>(b2, out);

    cudaEventDestroy(evFork);
    cudaEventDestroy(evJoin);
    cudaStreamDestroy(s2);
}

// round 11
// speedup vs baseline: 2.7415x; 1.4360x over previous
#include <cuda_runtime.h>
#include <cuda_fp16.h>
#include <cstdint>

// ---------------------------------------------------------------------------
// 2-layer GCN:  out = Â( relu( Â(xW1)+b1 ) W2 ) + b2,  Â = D^-1/2 (A+I) D^-1/2
// edge_index is INT32.
// GEMMs: HMMA mma.sync.m16n8k16 (fp16 in, fp32 accum), H stored fp16.
// Aggregation: CSR, warp-per-node, fp32 accumulate; layer-1 agg writes
// relu(a1) as fp16 (g_r1) = GEMM2's A operand. CSR build overlapped w/ GEMM1.
// ---------------------------------------------------------------------------

static constexpr int NN = 100000;
static constexpr int NE = 1600000;
static constexpr int SCAN_B = (NN + 1023) / 1024;   // 98 blocks

__device__ __half g_hh1[(size_t)NN * 128];  // x @ W1            (fp16)
__device__ __half g_r1[(size_t)NN * 128];   // relu(Â h1 + b1)   (fp16)
__device__ __half g_hh2[(size_t)NN * 64];   // relu(a1) @ W2     (fp16)
__device__ float  g_dis[NN];                // (1+indeg)^-1/2
__device__ int    g_indeg[NN];
__device__ int    g_incl[NN];
__device__ int    g_bsum[SCAN_B];
__device__ int    g_rowptr[NN + 1];
__device__ int    g_cursor[NN];
__device__ int    g_csrc[NE];               // CSR src ids (grouped by dst)

// ---------------------------------------------------------------------------
// helpers
// ---------------------------------------------------------------------------
__device__ __forceinline__ unsigned h2u(__half2 h) {
    return *reinterpret_cast<unsigned*>(&h);
}
__device__ __forceinline__ float2 u2f2(unsigned u) {
    return __half22float2(*reinterpret_cast<__half2*>(&u));
}
__device__ __forceinline__ void mma16816(float* c, const unsigned* a,
                                         const unsigned* b) {
    asm volatile(
        "mma.sync.aligned.m16n8k16.row.col.f32.f16.f16.f32 "
        "{%0,%1,%2,%3}, {%4,%5,%6,%7}, {%8,%9}, {%0,%1,%2,%3};"
        : "+f"(c[0]), "+f"(c[1]), "+f"(c[2]), "+f"(c[3])
        : "r"(a[0]), "r"(a[1]), "r"(a[2]), "r"(a[3]), "r"(b[0]), "r"(b[1]));
}

// ---------------------------------------------------------------------------
// degree / normalization
// ---------------------------------------------------------------------------
__global__ void k_zero_indeg() {
    int i = blockIdx.x * blockDim.x + threadIdx.x;
    if (i < NN) g_indeg[i] = 0;
}

__global__ void k_deg_count(const int* __restrict__ ei) {
    int e = blockIdx.x * blockDim.x + threadIdx.x;
    if (e < NE) atomicAdd(&g_indeg[ei[NE + e]], 1);
}

__global__ void k_dis() {
    int i = blockIdx.x * blockDim.x + threadIdx.x;
    if (i < NN) g_dis[i] = rsqrtf((float)(g_indeg[i] + 1));   // +1 self-loop
}

// ---------------------------------------------------------------------------
// multi-block exclusive scan of indeg -> rowptr (3 launches)
// ---------------------------------------------------------------------------
__global__ void __launch_bounds__(1024) k_scan_blk() {
    __shared__ int sh[1024];
    int t   = threadIdx.x;
    int idx = blockIdx.x * 1024 + t;
    int v   = (idx < NN) ? g_indeg[idx] : 0;
    sh[t] = v;
    __syncthreads();
#pragma unroll
    for (int off = 1; off < 1024; off <<= 1) {
        int tmp = (t >= off) ? sh[t - off] : 0;
        __syncthreads();
        sh[t] += tmp;
        __syncthreads();
    }
    if (idx < NN) g_incl[idx] = sh[t];
    if (t == 1023) g_bsum[blockIdx.x] = sh[1023];
}

__global__ void __launch_bounds__(128) k_scan_top() {
    __shared__ int sh[128];
    int t = threadIdx.x;
    int v = (t < SCAN_B) ? g_bsum[t] : 0;
    sh[t] = v;
    __syncthreads();
#pragma unroll
    for (int off = 1; off < 128; off <<= 1) {
        int tmp = (t >= off) ? sh[t - off] : 0;
        __syncthreads();
        sh[t] += tmp;
        __syncthreads();
    }
    if (t < SCAN_B) g_bsum[t] = sh[t] - v;        // exclusive block offset
    if (t == SCAN_B - 1) g_rowptr[NN] = sh[t];
}

__global__ void __launch_bounds__(1024) k_scan_fin() {
    int idx = blockIdx.x * 1024 + threadIdx.x;
    if (idx < NN) {
        int r = g_incl[idx] - g_indeg[idx] + g_bsum[blockIdx.x];
        g_rowptr[idx] = r;
        g_cursor[idx] = r;
    }
}

__global__ void k_csr_fill(const int* __restrict__ ei) {
    int e = blockIdx.x * blockDim.x + threadIdx.x;
    if (e < NE) {
        int s = ei[e];
        int d = ei[NE + e];
        int pos = atomicAdd(&g_cursor[d], 1);
        g_csrc[pos] = s;
    }
}

// ---------------------------------------------------------------------------
// HMMA GEMM: H[M,BN] = A[M,128] @ W[128,BN], fp16 inputs, fp32 accum, fp16 out.
// 256 thr = 8 warps (4m x 2n), BM=128, warp tile 32 x BN/2, KC=64 chunks.
// SRC=0: A = x (fp32 param, converted);  SRC=1: A = g_r1 (fp16).
// ---------------------------------------------------------------------------
template <int BN, int SRC>
__global__ void __launch_bounds__(256, 2)
k_gemm_mma(const float* __restrict__ Ap, const float* __restrict__ W, int M) {
    constexpr int K   = 128;
    constexpr int KC  = 64;
    constexpr int BM  = 128;
    constexpr int SA  = KC + 8;          // 72 halfs (conflict-free fragments)
    constexpr int SB  = KC + 8;
    constexpr int WN  = BN / 2;          // warp n-tile (64 or 32)
    constexpr int NT  = WN / 8;          // n8 tiles per warp (8 or 4)

    __shared__ __half As[BM * SA];       // [m][k]
    __shared__ __half Bs[BN * SB];       // [n][k]  (transposed for col-major B)

    const int tid  = threadIdx.x;
    const int wid  = tid >> 5;
    const int lane = tid & 31;
    const int gid  = lane >> 2;          // 0..7
    const int tig  = lane & 3;           // 0..3
    const int wm   = wid >> 1;           // 0..3
    const int wn   = wid & 1;            // 0..1
    const int rowbase = blockIdx.x * BM;

    float acc[2][NT][4];
#pragma unroll
    for (int mi = 0; mi < 2; mi++)
#pragma unroll
        for (int nj = 0; nj < NT; nj++)
#pragma unroll
            for (int q = 0; q < 4; q++) acc[mi][nj][q] = 0.f;

    for (int kk = 0; kk < K; kk += KC) {
        // --- A chunk (BM x 64) -> As[m][k] fp16 ---
        if (SRC == 0) {
            const float4* A4 = (const float4*)Ap;
#pragma unroll
            for (int t = 0; t < 8; t++) {
                int f  = tid + t * 256;
                int r  = f >> 4;             // 16 float4 per 64-col row
                int c4 = f & 15;
                int grow = rowbase + r;
                float4 v = make_float4(0.f, 0.f, 0.f, 0.f);
                if (grow < M) v = A4[(size_t)grow * 32 + (kk >> 2) + c4];
                uint2 pk;
                pk.x = h2u(__floats2half2_rn(v.x, v.y));
                pk.y = h2u(__floats2half2_rn(v.z, v.w));
                *(uint2*)&As[r * SA + c4 * 4] = pk;
            }
        } else {
            const uint2* A2 = (const uint2*)g_r1;   // 4 halfs per uint2, 32/row
#pragma unroll
            for (int t = 0; t < 8; t++) {
                int f  = tid + t * 256;
                int r  = f >> 4;
                int c4 = f & 15;
                int grow = rowbase + r;
                uint2 v = make_uint2(0u, 0u);
                if (grow < M) v = A2[(size_t)grow * 32 + (kk >> 2) + c4];
                *(uint2*)&As[r * SA + c4 * 4] = v;
            }
        }
        // --- W chunk (64 x BN) -> Bs[n][k] fp16 (transpose; coalesced reads) ---
        {
            constexpr int TPN  = 256 / BN;     // threads per n (2 or 4)
            constexpr int KPER = KC / TPN;     // k's per thread (32 or 16)
            int n  = tid % BN;
            int kb = (tid / BN) * KPER;
#pragma unroll
            for (int i = 0; i < KPER; i++) {
                float v = W[(size_t)(kk + kb + i) * BN + n];
                Bs[n * SB + kb + i] = __float2half_rn(v);
            }
        }
        __syncthreads();

#pragma unroll
        for (int ks = 0; ks < KC / 16; ks++) {
            unsigned a[2][4];
#pragma unroll
            for (int mi = 0; mi < 2; mi++) {
                const __half* base =
                    &As[(wm * 32 + mi * 16 + gid) * SA + ks * 16 + tig * 2];
                a[mi][0] = *(const unsigned*)base;
                a[mi][1] = *(const unsigned*)(base + 8 * SA);
                a[mi][2] = *(const unsigned*)(base + 8);
                a[mi][3] = *(const unsigned*)(base + 8 * SA + 8);
            }
#pragma unroll
            for (int nj = 0; nj < NT; nj++) {
                const __half* bb =
                    &Bs[(wn * WN + nj * 8 + gid) * SB + ks * 16 + tig * 2];
                unsigned b[2];
                b[0] = *(const unsigned*)bb;
                b[1] = *(const unsigned*)(bb + 8);
                mma16816(acc[0][nj], a[0], b);
                mma16816(acc[1][nj], a[1], b);
            }
        }
        __syncthreads();
    }

    // --- epilogue: fp16 store of H ---
    __half* H = (SRC == 0) ? g_hh1 : g_hh2;
#pragma unroll
    for (int mi = 0; mi < 2; mi++) {
#pragma unroll
        for (int rr = 0; rr < 2; rr++) {
            int grow = rowbase + wm * 32 + mi * 16 + gid + rr * 8;
            if (grow < M) {
#pragma unroll
                for (int nj = 0; nj < NT; nj++) {
                    int n = wn * WN + nj * 8 + tig * 2;
                    *(unsigned*)&H[(size_t)grow * BN + n] =
                        h2u(__floats2half2_rn(acc[mi][nj][rr * 2],
                                              acc[mi][nj][rr * 2 + 1]));
                }
            }
        }
    }
}

// ---------------------------------------------------------------------------
// aggregation (full GCN conv from fp16 H, fp32 accumulate):
//   res[w] = dis[w]*(dis[w]*h[w] + Σ dis[s]*h[s]) + bias
// C=128: writes relu(res) fp16 -> g_r1;  C=64: writes res fp32 -> d_out
// ---------------------------------------------------------------------------
template <int C>
__global__ void __launch_bounds__(256)
k_agg(const float* __restrict__ bias, float* __restrict__ outp) {
    const __half* h = (C == 128) ? g_hh1 : g_hh2;

    const int w = (blockIdx.x * blockDim.x + threadIdx.x) >> 5;
    if (w >= NN) return;
    const int lane = threadIdx.x & 31;
    const int beg = g_rowptr[w];
    const int end = g_rowptr[w + 1];
    const float dw = g_dis[w];

    if constexpr (C == 128) {
        const uint2* h8 = (const uint2*)h;          // 4 halfs per uint2, 32/row
        uint2 raw = h8[(size_t)w * 32 + lane];
        float2 f0 = u2f2(raw.x), f1 = u2f2(raw.y);
        float4 acc = make_float4(f0.x * dw, f0.y * dw, f1.x * dw, f1.y * dw);
        int j = beg;
        for (; j + 3 < end; j += 4) {               // 4-way for MLP
            int   s0 = g_csrc[j],   s1 = g_csrc[j+1], s2 = g_csrc[j+2], s3 = g_csrc[j+3];
            float w0 = g_dis[s0],   w1 = g_dis[s1],   w2 = g_dis[s2],   w3 = g_dis[s3];
            uint2 r0 = __ldg(h8 + (size_t)s0 * 32 + lane);
            uint2 r1 = __ldg(h8 + (size_t)s1 * 32 + lane);
            uint2 r2 = __ldg(h8 + (size_t)s2 * 32 + lane);
            uint2 r3 = __ldg(h8 + (size_t)s3 * 32 + lane);
            float2 a0 = u2f2(r0.x), b0 = u2f2(r0.y);
            float2 a1 = u2f2(r1.x), b1 = u2f2(r1.y);
            float2 a2 = u2f2(r2.x), b2 = u2f2(r2.y);
            float2 a3 = u2f2(r3.x), b3 = u2f2(r3.y);
            acc.x = fmaf(a0.x, w0, acc.x); acc.y = fmaf(a0.y, w0, acc.y);
            acc.z = fmaf(b0.x, w0, acc.z); acc.w = fmaf(b0.y, w0, acc.w);
            acc.x = fmaf(a1.x, w1, acc.x); acc.y = fmaf(a1.y, w1, acc.y);
            acc.z = fmaf(b1.x, w1, acc.z); acc.w = fmaf(b1.y, w1, acc.w);
            acc.x = fmaf(a2.x, w2, acc.x); acc.y = fmaf(a2.y, w2, acc.y);
            acc.z = fmaf(b2.x, w2, acc.z); acc.w = fmaf(b2.y, w2, acc.w);
            acc.x = fmaf(a3.x, w3, acc.x); acc.y = fmaf(a3.y, w3, acc.y);
            acc.z = fmaf(b3.x, w3, acc.z); acc.w = fmaf(b3.y, w3, acc.w);
        }
        for (; j < end; j++) {
            int   s0 = g_csrc[j];
            float w0 = g_dis[s0];
            uint2 r0 = __ldg(h8 + (size_t)s0 * 32 + lane);
            float2 a0 = u2f2(r0.x), b0 = u2f2(r0.y);
            acc.x = fmaf(a0.x, w0, acc.x); acc.y = fmaf(a0.y, w0, acc.y);
            acc.z = fmaf(b0.x, w0, acc.z); acc.w = fmaf(b0.y, w0, acc.w);
        }
        const float4 bb = ((const float4*)bias)[lane];
        float rx = fmaxf(fmaf(acc.x, dw, bb.x), 0.f);
        float ry = fmaxf(fmaf(acc.y, dw, bb.y), 0.f);
        float rz = fmaxf(fmaf(acc.z, dw, bb.z), 0.f);
        float rw = fmaxf(fmaf(acc.w, dw, bb.w), 0.f);
        uint2 pk;
        pk.x = h2u(__floats2half2_rn(rx, ry));
        pk.y = h2u(__floats2half2_rn(rz, rw));
        ((uint2*)g_r1)[(size_t)w * 32 + lane] = pk;   // relu(a1) in fp16
    } else {
        const unsigned* h4 = (const unsigned*)h;    // 2 halfs per u32, 32/row
        float2 hv = u2f2(h4[(size_t)w * 32 + lane]);
        float2 acc = make_float2(hv.x * dw, hv.y * dw);
        int j = beg;
        for (; j + 3 < end; j += 4) {
            int   s0 = g_csrc[j],   s1 = g_csrc[j+1], s2 = g_csrc[j+2], s3 = g_csrc[j+3];
            float w0 = g_dis[s0],   w1 = g_dis[s1],   w2 = g_dis[s2],   w3 = g_dis[s3];
            float2 v0 = u2f2(__ldg(h4 + (size_t)s0 * 32 + lane));
            float2 v1 = u2f2(__ldg(h4 + (size_t)s1 * 32 + lane));
            float2 v2 = u2f2(__ldg(h4 + (size_t)s2 * 32 + lane));
            float2 v3 = u2f2(__ldg(h4 + (size_t)s3 * 32 + lane));
            acc.x = fmaf(v0.x, w0, acc.x); acc.y = fmaf(v0.y, w0, acc.y);
            acc.x = fmaf(v1.x, w1, acc.x); acc.y = fmaf(v1.y, w1, acc.y);
            acc.x = fmaf(v2.x, w2, acc.x); acc.y = fmaf(v2.y, w2, acc.y);
            acc.x = fmaf(v3.x, w3, acc.x); acc.y = fmaf(v3.y, w3, acc.y);
        }
        for (; j < end; j++) {
            int   s0 = g_csrc[j];
            float w0 = g_dis[s0];
            float2 v0 = u2f2(__ldg(h4 + (size_t)s0 * 32 + lane));
            acc.x = fmaf(v0.x, w0, acc.x); acc.y = fmaf(v0.y, w0, acc.y);
        }
        const float2 bb = ((const float2*)bias)[lane];
        ((float2*)outp)[(size_t)w * 32 + lane] =
            make_float2(fmaf(acc.x, dw, bb.x), fmaf(acc.y, dw, bb.y));
    }
}

// ---------------------------------------------------------------------------
extern "C" void kernel_launch(void* const* d_in, const int* in_sizes, int n_in,
                              void* d_out, int out_size) {
    (void)in_sizes; (void)n_in; (void)out_size;
    const float* x  = (const float*)d_in[0];
    const int*   ei = (const int*)d_in[1];     // int32 (JAX x64 disabled)
    const float* W1 = (const float*)d_in[2];
    const float* b1 = (const float*)d_in[3];
    const float* W2 = (const float*)d_in[4];
    const float* b2 = (const float*)d_in[5];
    float* out = (float*)d_out;

    // fork-join: CSR build on side stream, overlapped with GEMM1
    cudaStream_t s2;
    cudaEvent_t evFork, evJoin;
    cudaStreamCreateWithFlags(&s2, cudaStreamNonBlocking);
    cudaEventCreateWithFlags(&evFork, cudaEventDisableTiming);
    cudaEventCreateWithFlags(&evJoin, cudaEventDisableTiming);

    cudaEventRecord(evFork, 0);
    cudaStreamWaitEvent(s2, evFork, 0);

    // --- CSR branch (stream s2): degrees, dis, rowptr, fill ---
    k_zero_indeg<<<(NN + 255) / 256, 256, 0, s2>>>();
    k_deg_count<<<(NE + 255) / 256, 256, 0, s2>>>(ei);
    k_dis<<<(NN + 255) / 256, 256, 0, s2>>>();
    k_scan_blk<<<SCAN_B, 1024, 0, s2>>>();
    k_scan_top<<<1, 128, 0, s2>>>();
    k_scan_fin<<<SCAN_B, 1024, 0, s2>>>();
    k_csr_fill<<<(NE + 255) / 256, 256, 0, s2>>>(ei);
    cudaEventRecord(evJoin, s2);

    // --- main branch (stream 0): GEMM1 overlapped with CSR build ---
    k_gemm_mma<128, 0><<<(NN + 127) / 128, 256>>>(x, W1, NN);
    cudaStreamWaitEvent(0, evJoin, 0);

    k_agg<128><<<(NN * 32 + 255) / 256, 256>>>(b1, nullptr);
    k_gemm_mma<64, 1><<<(NN + 127) / 128, 256>>>(nullptr, W2, NN);
    k_agg<64><<<(NN * 32 + 255) / 256, 256>>>(b2, out);

    cudaEventDestroy(evFork);
    cudaEventDestroy(evJoin);
    cudaStreamDestroy(s2);
}

// round 12
// speedup vs baseline: 2.8595x; 1.0430x over previous
#include <cuda_runtime.h>
#include <cuda_fp16.h>
#include <cstdint>

// ---------------------------------------------------------------------------
// 2-layer GCN:  out = Â( relu( Â(xW1)+b1 ) W2 ) + b2,  Â = D^-1/2 (A+I) D^-1/2
// edge_index is INT32.
// GEMMs: HMMA mma.sync.m16n8k16 (fp16 in, fp32 accum), H stored fp16.
// GEMM2 epilogue pre-scales rows by dis[row] -> agg64 needs no per-edge dis.
// Aggregation: CSR, warp-per-node, fp32 accumulate; layer-1 agg emits
// relu(a1) fp16 (g_r1). CSR build (warp-shuffle scans) overlapped w/ GEMM1.
// ---------------------------------------------------------------------------

static constexpr int NN = 100000;
static constexpr int NE = 1600000;
static constexpr int SCAN_B = (NN + 1023) / 1024;   // 98 blocks

__device__ __half g_hh1[(size_t)NN * 128];  // x @ W1                  (fp16)
__device__ __half g_r1[(size_t)NN * 128];   // relu(Â h1 + b1)         (fp16)
__device__ __half g_hh2[(size_t)NN * 64];   // dis[row]*(relu(a1)@W2)  (fp16)
__device__ float  g_dis[NN];                // (1+indeg)^-1/2
__device__ int    g_indeg[NN];
__device__ int    g_incl[NN];
__device__ int    g_bsum[SCAN_B];
__device__ int    g_rowptr[NN + 1];
__device__ int    g_cursor[NN];
__device__ int    g_csrc[NE];               // CSR src ids (grouped by dst)

// ---------------------------------------------------------------------------
// helpers
// ---------------------------------------------------------------------------
__device__ __forceinline__ unsigned h2u(__half2 h) {
    return *reinterpret_cast<unsigned*>(&h);
}
__device__ __forceinline__ float2 u2f2(unsigned u) {
    return __half22float2(*reinterpret_cast<__half2*>(&u));
}
__device__ __forceinline__ void mma16816(float* c, const unsigned* a,
                                         const unsigned* b) {
    asm volatile(
        "mma.sync.aligned.m16n8k16.row.col.f32.f16.f16.f32 "
        "{%0,%1,%2,%3}, {%4,%5,%6,%7}, {%8,%9}, {%0,%1,%2,%3};"
        : "+f"(c[0]), "+f"(c[1]), "+f"(c[2]), "+f"(c[3])
        : "r"(a[0]), "r"(a[1]), "r"(a[2]), "r"(a[3]), "r"(b[0]), "r"(b[1]));
}

// ---------------------------------------------------------------------------
// degree count (int4-vectorized; NE % 4 == 0)
// ---------------------------------------------------------------------------
__global__ void k_zero_indeg() {
    int i = blockIdx.x * blockDim.x + threadIdx.x;
    if (i < NN) g_indeg[i] = 0;
}

__global__ void k_deg_count(const int* __restrict__ ei) {
    int i = blockIdx.x * blockDim.x + threadIdx.x;
    if (i < NE / 4) {
        int4 d = ((const int4*)(ei + NE))[i];
        atomicAdd(&g_indeg[d.x], 1);
        atomicAdd(&g_indeg[d.y], 1);
        atomicAdd(&g_indeg[d.z], 1);
        atomicAdd(&g_indeg[d.w], 1);
    }
}

// ---------------------------------------------------------------------------
// scan (2-level warp shuffle) + dis fused into pass 1
// ---------------------------------------------------------------------------
__global__ void __launch_bounds__(1024) k_scan_blk() {
    __shared__ int wsum[32];
    const int t = threadIdx.x, lane = t & 31, wid = t >> 5;
    const int idx = blockIdx.x * 1024 + t;
    int deg = (idx < NN) ? g_indeg[idx] : 0;
    if (idx < NN) g_dis[idx] = rsqrtf((float)(deg + 1));   // fused k_dis
    int s = deg;
#pragma unroll
    for (int o = 1; o < 32; o <<= 1) {
        int n = __shfl_up_sync(0xffffffffu, s, o);
        if (lane >= o) s += n;
    }
    if (lane == 31) wsum[wid] = s;
    __syncthreads();
    if (wid == 0) {
        int ws = wsum[lane];
#pragma unroll
        for (int o = 1; o < 32; o <<= 1) {
            int n = __shfl_up_sync(0xffffffffu, ws, o);
            if (lane >= o) ws += n;
        }
        wsum[lane] = ws;
    }
    __syncthreads();
    int incl = (wid ? wsum[wid - 1] : 0) + s;
    if (idx < NN) g_incl[idx] = incl;
    if (t == 1023) g_bsum[blockIdx.x] = incl;
}

__global__ void __launch_bounds__(128) k_scan_top() {
    __shared__ int wsum[4];
    const int t = threadIdx.x, lane = t & 31, wid = t >> 5;
    int v = (t < SCAN_B) ? g_bsum[t] : 0;
    int s = v;
#pragma unroll
    for (int o = 1; o < 32; o <<= 1) {
        int n = __shfl_up_sync(0xffffffffu, s, o);
        if (lane >= o) s += n;
    }
    if (lane == 31) wsum[wid] = s;
    __syncthreads();
    if (wid == 0 && lane < 4) {
        int ws = wsum[lane];
#pragma unroll
        for (int o = 1; o < 4; o <<= 1) {
            int n = __shfl_up_sync(0x0000000fu, ws, o);
            if (lane >= o) ws += n;
        }
        wsum[lane] = ws;
    }
    __syncthreads();
    int incl = (wid ? wsum[wid - 1] : 0) + s;
    if (t < SCAN_B) g_bsum[t] = incl - v;          // exclusive block offset
    if (t == SCAN_B - 1) g_rowptr[NN] = incl;
}

__global__ void __launch_bounds__(1024) k_scan_fin() {
    int idx = blockIdx.x * 1024 + threadIdx.x;
    if (idx < NN) {
        int r = g_incl[idx] - g_indeg[idx] + g_bsum[blockIdx.x];
        g_rowptr[idx] = r;
        g_cursor[idx] = r;
    }
}

__global__ void k_csr_fill(const int* __restrict__ ei) {
    int i = blockIdx.x * blockDim.x + threadIdx.x;
    if (i < NE / 2) {
        int2 s = ((const int2*)ei)[i];
        int2 d = ((const int2*)(ei + NE))[i];
        int p0 = atomicAdd(&g_cursor[d.x], 1);
        g_csrc[p0] = s.x;
        int p1 = atomicAdd(&g_cursor[d.y], 1);
        g_csrc[p1] = s.y;
    }
}

// ---------------------------------------------------------------------------
// HMMA GEMM: H[M,BN] = A[M,128] @ W[128,BN], fp16 inputs, fp32 accum, fp16 out.
// 256 thr = 8 warps (4m x 2n), BM=128, warp tile 32 x BN/2, KC=64 chunks.
// SRC=0: A = x (fp32 param, converted), store h.
// SRC=1: A = g_r1 (fp16), store dis[row]*h   (pre-scaled for agg64).
// ---------------------------------------------------------------------------
template <int BN, int SRC>
__global__ void __launch_bounds__(256, 2)
k_gemm_mma(const float* __restrict__ Ap, const float* __restrict__ W, int M) {
    constexpr int K   = 128;
    constexpr int KC  = 64;
    constexpr int BM  = 128;
    constexpr int SA  = KC + 8;          // 72 halfs (conflict-free fragments)
    constexpr int SB  = KC + 8;
    constexpr int WN  = BN / 2;          // warp n-tile (64 or 32)
    constexpr int NT  = WN / 8;          // n8 tiles per warp (8 or 4)

    __shared__ __half As[BM * SA];       // [m][k]
    __shared__ __half Bs[BN * SB];       // [n][k]  (transposed for col-major B)

    const int tid  = threadIdx.x;
    const int wid  = tid >> 5;
    const int lane = tid & 31;
    const int gid  = lane >> 2;          // 0..7
    const int tig  = lane & 3;           // 0..3
    const int wm   = wid >> 1;           // 0..3
    const int wn   = wid & 1;            // 0..1
    const int rowbase = blockIdx.x * BM;

    float acc[2][NT][4];
#pragma unroll
    for (int mi = 0; mi < 2; mi++)
#pragma unroll
        for (int nj = 0; nj < NT; nj++)
#pragma unroll
            for (int q = 0; q < 4; q++) acc[mi][nj][q] = 0.f;

    for (int kk = 0; kk < K; kk += KC) {
        // --- A chunk (BM x 64) -> As[m][k] fp16 ---
        if (SRC == 0) {
            const float4* A4 = (const float4*)Ap;
#pragma unroll
            for (int t = 0; t < 8; t++) {
                int f  = tid + t * 256;
                int r  = f >> 4;             // 16 float4 per 64-col row
                int c4 = f & 15;
                int grow = rowbase + r;
                float4 v = make_float4(0.f, 0.f, 0.f, 0.f);
                if (grow < M) v = A4[(size_t)grow * 32 + (kk >> 2) + c4];
                uint2 pk;
                pk.x = h2u(__floats2half2_rn(v.x, v.y));
                pk.y = h2u(__floats2half2_rn(v.z, v.w));
                *(uint2*)&As[r * SA + c4 * 4] = pk;
            }
        } else {
            const uint2* A2 = (const uint2*)g_r1;   // 4 halfs per uint2, 32/row
#pragma unroll
            for (int t = 0; t < 8; t++) {
                int f  = tid + t * 256;
                int r  = f >> 4;
                int c4 = f & 15;
                int grow = rowbase + r;
                uint2 v = make_uint2(0u, 0u);
                if (grow < M) v = A2[(size_t)grow * 32 + (kk >> 2) + c4];
                *(uint2*)&As[r * SA + c4 * 4] = v;
            }
        }
        // --- W chunk (64 x BN) -> Bs[n][k] fp16 (transpose; coalesced reads) ---
        {
            constexpr int TPN  = 256 / BN;     // threads per n (2 or 4)
            constexpr int KPER = KC / TPN;     // k's per thread (32 or 16)
            int n  = tid % BN;
            int kb = (tid / BN) * KPER;
#pragma unroll
            for (int i = 0; i < KPER; i++) {
                float v = W[(size_t)(kk + kb + i) * BN + n];
                Bs[n * SB + kb + i] = __float2half_rn(v);
            }
        }
        __syncthreads();

#pragma unroll
        for (int ks = 0; ks < KC / 16; ks++) {
            unsigned a[2][4];
#pragma unroll
            for (int mi = 0; mi < 2; mi++) {
                const __half* base =
                    &As[(wm * 32 + mi * 16 + gid) * SA + ks * 16 + tig * 2];
                a[mi][0] = *(const unsigned*)base;
                a[mi][1] = *(const unsigned*)(base + 8 * SA);
                a[mi][2] = *(const unsigned*)(base + 8);
                a[mi][3] = *(const unsigned*)(base + 8 * SA + 8);
            }
#pragma unroll
            for (int nj = 0; nj < NT; nj++) {
                const __half* bb =
                    &Bs[(wn * WN + nj * 8 + gid) * SB + ks * 16 + tig * 2];
                unsigned b[2];
                b[0] = *(const unsigned*)bb;
                b[1] = *(const unsigned*)(bb + 8);
                mma16816(acc[0][nj], a[0], b);
                mma16816(acc[1][nj], a[1], b);
            }
        }
        __syncthreads();
    }

    // --- epilogue: fp16 store of H (SRC==1: pre-scaled by dis[row]) ---
    __half* H = (SRC == 0) ? g_hh1 : g_hh2;
#pragma unroll
    for (int mi = 0; mi < 2; mi++) {
#pragma unroll
        for (int rr = 0; rr < 2; rr++) {
            int grow = rowbase + wm * 32 + mi * 16 + gid + rr * 8;
            if (grow < M) {
                float sc = (SRC == 1) ? g_dis[grow] : 1.0f;
#pragma unroll
                for (int nj = 0; nj < NT; nj++) {
                    int n = wn * WN + nj * 8 + tig * 2;
                    float v0 = acc[mi][nj][rr * 2];
                    float v1 = acc[mi][nj][rr * 2 + 1];
                    if (SRC == 1) { v0 *= sc; v1 *= sc; }
                    *(unsigned*)&H[(size_t)grow * BN + n] =
                        h2u(__floats2half2_rn(v0, v1));
                }
            }
        }
    }
}

// ---------------------------------------------------------------------------
// aggregation, warp-per-node, fp32 accumulate.
// C=128 (h=g_hh1, raw):  r1[w] = relu( dw*(dw*h[w] + Σ dis[s]*h[s]) + b )  fp16
// C=64  (h=g_hh2, PRE-SCALED by dis): out[w] = dw*(hh2[w] + Σ hh2[s]) + b  fp32
// ---------------------------------------------------------------------------
template <int C>
__global__ void __launch_bounds__(256)
k_agg(const float* __restrict__ bias, float* __restrict__ outp) {
    const __half* h = (C == 128) ? g_hh1 : g_hh2;

    const int w = (blockIdx.x * blockDim.x + threadIdx.x) >> 5;
    if (w >= NN) return;
    const int lane = threadIdx.x & 31;
    const int beg = g_rowptr[w];
    const int end = g_rowptr[w + 1];
    const float dw = g_dis[w];

    if constexpr (C == 128) {
        const uint2* h8 = (const uint2*)h;          // 4 halfs per uint2, 32/row
        uint2 raw = h8[(size_t)w * 32 + lane];
        float2 f0 = u2f2(raw.x), f1 = u2f2(raw.y);
        float4 acc = make_float4(f0.x * dw, f0.y * dw, f1.x * dw, f1.y * dw);
        int j = beg;
        for (; j + 3 < end; j += 4) {               // 4-way for MLP
            int   s0 = g_csrc[j],   s1 = g_csrc[j+1], s2 = g_csrc[j+2], s3 = g_csrc[j+3];
            float w0 = g_dis[s0],   w1 = g_dis[s1],   w2 = g_dis[s2],   w3 = g_dis[s3];
            uint2 r0 = __ldg(h8 + (size_t)s0 * 32 + lane);
            uint2 r1 = __ldg(h8 + (size_t)s1 * 32 + lane);
            uint2 r2 = __ldg(h8 + (size_t)s2 * 32 + lane);
            uint2 r3 = __ldg(h8 + (size_t)s3 * 32 + lane);
            float2 a0 = u2f2(r0.x), b0 = u2f2(r0.y);
            float2 a1 = u2f2(r1.x), b1 = u2f2(r1.y);
            float2 a2 = u2f2(r2.x), b2 = u2f2(r2.y);
            float2 a3 = u2f2(r3.x), b3 = u2f2(r3.y);
            acc.x = fmaf(a0.x, w0, acc.x); acc.y = fmaf(a0.y, w0, acc.y);
            acc.z = fmaf(b0.x, w0, acc.z); acc.w = fmaf(b0.y, w0, acc.w);
            acc.x = fmaf(a1.x, w1, acc.x); acc.y = fmaf(a1.y, w1, acc.y);
            acc.z = fmaf(b1.x, w1, acc.z); acc.w = fmaf(b1.y, w1, acc.w);
            acc.x = fmaf(a2.x, w2, acc.x); acc.y = fmaf(a2.y, w2, acc.y);
            acc.z = fmaf(b2.x, w2, acc.z); acc.w = fmaf(b2.y, w2, acc.w);
            acc.x = fmaf(a3.x, w3, acc.x); acc.y = fmaf(a3.y, w3, acc.y);
            acc.z = fmaf(b3.x, w3, acc.z); acc.w = fmaf(b3.y, w3, acc.w);
        }
        for (; j < end; j++) {
            int   s0 = g_csrc[j];
            float w0 = g_dis[s0];
            uint2 r0 = __ldg(h8 + (size_t)s0 * 32 + lane);
            float2 a0 = u2f2(r0.x), b0 = u2f2(r0.y);
            acc.x = fmaf(a0.x, w0, acc.x); acc.y = fmaf(a0.y, w0, acc.y);
            acc.z = fmaf(b0.x, w0, acc.z); acc.w = fmaf(b0.y, w0, acc.w);
        }
        const float4 bb = ((const float4*)bias)[lane];
        float rx = fmaxf(fmaf(acc.x, dw, bb.x), 0.f);
        float ry = fmaxf(fmaf(acc.y, dw, bb.y), 0.f);
        float rz = fmaxf(fmaf(acc.z, dw, bb.z), 0.f);
        float rw = fmaxf(fmaf(acc.w, dw, bb.w), 0.f);
        uint2 pk;
        pk.x = h2u(__floats2half2_rn(rx, ry));
        pk.y = h2u(__floats2half2_rn(rz, rw));
        ((uint2*)g_r1)[(size_t)w * 32 + lane] = pk;   // relu(a1) in fp16
    } else {
        const unsigned* h4 = (const unsigned*)h;    // 2 halfs per u32, 32/row
        float2 hv = u2f2(h4[(size_t)w * 32 + lane]);
        float2 acc = hv;                            // hh2[w] = dw*h2[w] already
        int j = beg;
        for (; j + 3 < end; j += 4) {
            int s0 = g_csrc[j], s1 = g_csrc[j+1], s2 = g_csrc[j+2], s3 = g_csrc[j+3];
            float2 v0 = u2f2(__ldg(h4 + (size_t)s0 * 32 + lane));
            float2 v1 = u2f2(__ldg(h4 + (size_t)s1 * 32 + lane));
            float2 v2 = u2f2(__ldg(h4 + (size_t)s2 * 32 + lane));
            float2 v3 = u2f2(__ldg(h4 + (size_t)s3 * 32 + lane));
            acc.x += v0.x + v1.x; acc.y += v0.y + v1.y;
            acc.x += v2.x + v3.x; acc.y += v2.y + v3.y;
        }
        for (; j < end; j++) {
            int s0 = g_csrc[j];
            float2 v0 = u2f2(__ldg(h4 + (size_t)s0 * 32 + lane));
            acc.x += v0.x; acc.y += v0.y;
        }
        const float2 bb = ((const float2*)bias)[lane];
        ((float2*)outp)[(size_t)w * 32 + lane] =
            make_float2(fmaf(acc.x, dw, bb.x), fmaf(acc.y, dw, bb.y));
    }
}

// ---------------------------------------------------------------------------
extern "C" void kernel_launch(void* const* d_in, const int* in_sizes, int n_in,
                              void* d_out, int out_size) {
    (void)in_sizes; (void)n_in; (void)out_size;
    const float* x  = (const float*)d_in[0];
    const int*   ei = (const int*)d_in[1];     // int32 (JAX x64 disabled)
    const float* W1 = (const float*)d_in[2];
    const float* b1 = (const float*)d_in[3];
    const float* W2 = (const float*)d_in[4];
    const float* b2 = (const float*)d_in[5];
    float* out = (float*)d_out;

    // fork-join: CSR build on side stream, overlapped with GEMM1
    cudaStream_t s2;
    cudaEvent_t evFork, evJoin;
    cudaStreamCreateWithFlags(&s2, cudaStreamNonBlocking);
    cudaEventCreateWithFlags(&evFork, cudaEventDisableTiming);
    cudaEventCreateWithFlags(&evJoin, cudaEventDisableTiming);

    cudaEventRecord(evFork, 0);
    cudaStreamWaitEvent(s2, evFork, 0);

    // --- CSR branch (stream s2): degrees, scan(+dis), fill ---
    k_zero_indeg<<<(NN + 255) / 256, 256, 0, s2>>>();
    k_deg_count<<<(NE / 4 + 255) / 256, 256, 0, s2>>>(ei);
    k_scan_blk<<<SCAN_B, 1024, 0, s2>>>();
    k_scan_top<<<1, 128, 0, s2>>>();
    k_scan_fin<<<SCAN_B, 1024, 0, s2>>>();
    k_csr_fill<<<(NE / 2 + 255) / 256, 256, 0, s2>>>(ei);
    cudaEventRecord(evJoin, s2);

    // --- main branch (stream 0): GEMM1 overlapped with CSR build ---
    k_gemm_mma<128, 0><<<(NN + 127) / 128, 256>>>(x, W1, NN);
    cudaStreamWaitEvent(0, evJoin, 0);

    k_agg<128><<<(NN * 32 + 255) / 256, 256>>>(b1, nullptr);
    k_gemm_mma<64, 1><<<(NN + 127) / 128, 256>>>(nullptr, W2, NN);
    k_agg<64><<<(NN * 32 + 255) / 256, 256>>>(b2, out);

    cudaEventDestroy(evFork);
    cudaEventDestroy(evJoin);
    cudaStreamDestroy(s2);
}